// round 14
// baseline (speedup 1.0000x reference)
#include <cuda_runtime.h>
#include <math.h>
#include <stdint.h>

#define NOP 20000
#define NMM 500
#define DD  256
#define HH  8
#define DHD 32
#define TDE 16
#define EE  200000

#define TILES_OP 314   // 157 rowblocks x 2 colblocks
#define TILES_M  8     // 4 x 2
#define TILES_ALL (TILES_OP + TILES_M)

#define TEMP_BLOCKS 782            // ceil(EE/256), 256 edges per block
#define CNT_BPT 782                // count blocks per edge type: ceil(EE/256)
#define RELB_PER_H 313             // ceil(NOP/64) node-blocks per (type<3, head)
#define RELB_OP (RELB_PER_H * HH)  // 2504 per op-src type
#define RELB_M_PER_H 8             // ceil(NMM/64)
#define REL_TC (3 * RELB_OP + RELB_M_PER_H * HH)   // 7576
#define GOP_BLOCKS 2500            // NOP*32/256

// ---------------- scratch ----------------
__device__ float g_xw[NOP * DD];
__device__ float g_k_op[NOP * DD];
__device__ float g_q_op[NOP * DD];
__device__ float g_v_op[NOP * DD];
__device__ float g_k_m[NMM * DD];
__device__ float g_q_m[NMM * DD];
__device__ float g_v_m[NMM * DD];
__device__ float g_KT[3][NOP * DD];
__device__ float g_VT[3][NOP * DD];
__device__ float g_KTm[NMM * DD];
__device__ float g_VTm[NMM * DD];
__device__ float g_acc_op[NOP * DD];
__device__ float g_acc_m[NMM * DD];
__device__ int   g_off4[4][NOP + 1];
__device__ int   g_cur4[4][NOP];
__device__ int   g_esrc4[4][EE];

__device__ __forceinline__ float gelu_exact(float x) {
    return 0.5f * x * (1.0f + erff(x * 0.70710678118654752f));
}

__device__ __forceinline__ void red_add_v4(float* p, float a, float b, float c, float d) {
    asm volatile("red.global.add.v4.f32 [%0], {%1, %2, %3, %4};"
                 :: "l"(p), "f"(a), "f"(b), "f"(c), "f"(d) : "memory");
}

__device__ __forceinline__ uint32_t cvt_tf32(float x) {
    uint32_t r; asm("cvt.rna.tf32.f32 %0, %1;" : "=r"(r) : "f"(x)); return r;
}

__device__ __forceinline__ void mma_tf32(float* c, const uint32_t* a, const uint32_t* b) {
    asm volatile("mma.sync.aligned.m16n8k8.row.col.f32.tf32.tf32.f32 "
                 "{%0,%1,%2,%3}, {%4,%5,%6,%7}, {%8,%9}, {%0,%1,%2,%3};"
                 : "+f"(c[0]), "+f"(c[1]), "+f"(c[2]), "+f"(c[3])
                 : "r"(a[0]), "r"(a[1]), "r"(a[2]), "r"(a[3]),
                   "r"(b[0]), "r"(b[1]));
}

// ---------------- temporal encoding: 256 edges per block, 8 warps x 32 edges ----------------
__device__ void temporal_body(int blk,
                              const float* __restrict__ delta_t,
                              const int* __restrict__ ei_src,
                              const float* __restrict__ Wt,
                              const float* __restrict__ bt,
                              const float* __restrict__ ln_g,
                              const float* __restrict__ ln_b)
{
    __shared__ float Wts[TDE * DD];
    __shared__ float bts[DD], gs[DD], bs[DD];
    __shared__ float tr[8][DD];
    for (int idx = threadIdx.x; idx < DD * TDE; idx += blockDim.x) {
        int j = idx / TDE, i = idx % TDE;
        Wts[i * DD + j] = Wt[idx];
    }
    for (int idx = threadIdx.x; idx < DD; idx += blockDim.x) {
        bts[idx] = bt[idx]; gs[idx] = ln_g[idx]; bs[idx] = ln_b[idx];
    }
    __syncthreads();

    int warp = threadIdx.x >> 5;
    int lane = threadIdx.x & 31;

    float freqs[8];
    #pragma unroll
    for (int m = 0; m < 8; m++)
        freqs[m] = exp2f(-(float)m * (9.965784284662087f / 8.0f));  // 1000^{-m/8}

    #pragma unroll 1
    for (int t = 0; t < 32; t++) {
        int w = blk * 256 + warp * 32 + t;
        if (w >= EE) break;

        float dt = delta_t[w];
        int src = ei_src[w];

        float sn[8], cn[8];
        #pragma unroll
        for (int m = 0; m < 8; m++) sincosf(dt * freqs[m], &sn[m], &cn[m]);

        float pt[8];
        float lsum = 0.0f;
        #pragma unroll
        for (int jj = 0; jj < 8; jj++) {
            int j = lane + jj * 32;
            float s = bts[j];
            #pragma unroll
            for (int m = 0; m < 8; m++)
                s += sn[m] * Wts[(2 * m) * DD + j] + cn[m] * Wts[(2 * m + 1) * DD + j];
            pt[jj] = s;
            lsum += s;
        }
        #pragma unroll
        for (int o = 16; o; o >>= 1) lsum += __shfl_xor_sync(0xffffffffu, lsum, o);
        float mu = lsum * (1.0f / 256.0f);

        float lvar = 0.0f;
        #pragma unroll
        for (int jj = 0; jj < 8; jj++) { float d = pt[jj] - mu; lvar += d * d; }
        #pragma unroll
        for (int o = 16; o; o >>= 1) lvar += __shfl_xor_sync(0xffffffffu, lvar, o);
        float rstd = rsqrtf(lvar * (1.0f / 256.0f) + 1e-5f);

        #pragma unroll
        for (int jj = 0; jj < 8; jj++) {
            int j = lane + jj * 32;
            tr[warp][j] = (pt[jj] - mu) * rstd * gs[j] + bs[j];
        }
        __syncwarp();
        float4 y0 = *(const float4*)&tr[warp][lane * 8];
        float4 y1 = *(const float4*)&tr[warp][lane * 8 + 4];
        float* xp = &g_xw[(size_t)src * DD + lane * 8];
        red_add_v4(xp,     y0.x, y0.y, y0.z, y0.w);
        red_add_v4(xp + 4, y1.x, y1.y, y1.z, y1.w);
        __syncwarp();
    }
}

// ---------------- launch 1: temporal + CSR count ----------------
__global__ void __launch_bounds__(256) fused_temporal_count(
    const float* __restrict__ delta_t,
    const int* __restrict__ e0, const int* __restrict__ e1,
    const int* __restrict__ e2, const int* __restrict__ e3,
    const float* __restrict__ Wt, const float* __restrict__ bt,
    const float* __restrict__ ln_g, const float* __restrict__ ln_b)
{
    int b = blockIdx.x;
    if (b < TEMP_BLOCKS) {
        temporal_body(b, delta_t, e0, Wt, bt, ln_g, ln_b);
    } else {
        int cb = b - TEMP_BLOCKS;
        int ty = cb / CNT_BPT;
        int i = (cb % CNT_BPT) * 256 + threadIdx.x;
        if (i < EE) {
            const int* ei = (ty == 0) ? e0 : (ty == 1) ? e1 : (ty == 2) ? e2 : e3;
            atomicAdd(&g_cur4[ty][ei[EE + i]], 1);
        }
    }
}

// ---------------- tensor-core 3xTF32 GEMM tile: 128x128, K=256, pipelined ----------------
#define SMP 20

__device__ __forceinline__ void split_store(uint32_t* H, uint32_t* L, int idx, float4 v) {
    uint32_t h0 = cvt_tf32(v.x), h1 = cvt_tf32(v.y), h2 = cvt_tf32(v.z), h3 = cvt_tf32(v.w);
    uint32_t l0 = cvt_tf32(v.x - __uint_as_float(h0));
    uint32_t l1 = cvt_tf32(v.y - __uint_as_float(h1));
    uint32_t l2 = cvt_tf32(v.z - __uint_as_float(h2));
    uint32_t l3 = cvt_tf32(v.w - __uint_as_float(h3));
    *(uint4*)&H[idx] = make_uint4(h0, h1, h2, h3);
    *(uint4*)&L[idx] = make_uint4(l0, l1, l2, l3);
}

template <bool FUSE>
__device__ __forceinline__ void gemm_tile_tc(
    const float* __restrict__ A, const float* __restrict__ W,
    const float* __restrict__ bias, float* __restrict__ C, int N,
    const float* __restrict__ xsrc, float sa, int rowBase, int colBase)
{
    __shared__ uint32_t Ah[128 * SMP], Al[128 * SMP];
    __shared__ uint32_t Bh[128 * SMP], Bl[128 * SMP];

    int tid = threadIdx.x;
    int lane = tid & 31;
    int wid = tid >> 5;
    int mwarp = wid >> 2;
    int nwarp = wid & 3;
    int grp  = lane >> 2;
    int tid4 = lane & 3;

    int row0 = tid >> 2, q0 = (tid & 3) * 4;
    int row1 = row0 + 64;
    int gr0 = rowBase + row0, gr1 = rowBase + row1;
    int gc0 = colBase + row0, gc1 = colBase + row1;

    float acc[4][4][4];
    #pragma unroll
    for (int i = 0; i < 4; i++)
        #pragma unroll
        for (int j = 0; j < 4; j++)
            #pragma unroll
            for (int r = 0; r < 4; r++) acc[i][j][r] = 0.0f;

    float4 av0, av1, bv0, bv1;
    auto ldg = [&](int kt) {
        av0 = make_float4(0.f, 0.f, 0.f, 0.f);
        av1 = make_float4(0.f, 0.f, 0.f, 0.f);
        if (gr0 < N) av0 = *(const float4*)(A + (size_t)gr0 * 256 + kt + q0);
        if (gr1 < N) av1 = *(const float4*)(A + (size_t)gr1 * 256 + kt + q0);
        if (FUSE) {
            av0.x = gelu_exact(av0.x); av0.y = gelu_exact(av0.y);
            av0.z = gelu_exact(av0.z); av0.w = gelu_exact(av0.w);
            av1.x = gelu_exact(av1.x); av1.y = gelu_exact(av1.y);
            av1.z = gelu_exact(av1.z); av1.w = gelu_exact(av1.w);
        }
        bv0 = *(const float4*)(W + (size_t)gc0 * 256 + kt + q0);
        bv1 = *(const float4*)(W + (size_t)gc1 * 256 + kt + q0);
    };
    auto sts = [&]() {
        split_store(Ah, Al, row0 * SMP + q0, av0);
        split_store(Ah, Al, row1 * SMP + q0, av1);
        split_store(Bh, Bl, row0 * SMP + q0, bv0);
        split_store(Bh, Bl, row1 * SMP + q0, bv1);
    };

    ldg(0);
    sts();
    __syncthreads();

    for (int it = 0; it < 16; it++) {
        if (it < 15) ldg((it + 1) * 16);   // prefetch hides under mma

        #pragma unroll
        for (int s = 0; s < 2; s++) {
            int kb = s * 8 + tid4;
            uint32_t ah[4][4], al[4][4];
            #pragma unroll
            for (int mt = 0; mt < 4; mt++) {
                int base = (mwarp * 64 + mt * 16 + grp) * SMP + kb;
                ah[mt][0] = Ah[base];            al[mt][0] = Al[base];
                ah[mt][1] = Ah[base + 8 * SMP];  al[mt][1] = Al[base + 8 * SMP];
                ah[mt][2] = Ah[base + 4];        al[mt][2] = Al[base + 4];
                ah[mt][3] = Ah[base + 8 * SMP + 4]; al[mt][3] = Al[base + 8 * SMP + 4];
            }
            uint32_t bh[4][2], bl[4][2];
            #pragma unroll
            for (int nt = 0; nt < 4; nt++) {
                int base = (nwarp * 32 + nt * 8 + grp) * SMP + kb;
                bh[nt][0] = Bh[base];     bl[nt][0] = Bl[base];
                bh[nt][1] = Bh[base + 4]; bl[nt][1] = Bl[base + 4];
            }
            #pragma unroll
            for (int mt = 0; mt < 4; mt++)
                #pragma unroll
                for (int nt = 0; nt < 4; nt++) {
                    mma_tf32(acc[mt][nt], ah[mt], bh[nt]);
                    mma_tf32(acc[mt][nt], ah[mt], bl[nt]);
                    mma_tf32(acc[mt][nt], al[mt], bh[nt]);
                }
        }
        __syncthreads();
        if (it < 15) {
            sts();
            __syncthreads();
        }
    }

    #pragma unroll
    for (int mt = 0; mt < 4; mt++) {
        int r0g = rowBase + mwarp * 64 + mt * 16 + grp;
        int r1g = r0g + 8;
        #pragma unroll
        for (int nt = 0; nt < 4; nt++) {
            int c = colBase + nwarp * 32 + nt * 8 + tid4 * 2;
            float2 bi = *(const float2*)(bias + c);
            if (r0g < N) {
                float o0 = acc[mt][nt][0] + bi.x;
                float o1 = acc[mt][nt][1] + bi.y;
                if (FUSE) {
                    float2 xs = *(const float2*)(xsrc + (size_t)r0g * 256 + c);
                    o0 = sa * o0 + (1.0f - sa) * xs.x;
                    o1 = sa * o1 + (1.0f - sa) * xs.y;
                }
                *(float2*)(C + (size_t)r0g * 256 + c) = make_float2(o0, o1);
            }
            if (r1g < N) {
                float o2 = acc[mt][nt][2] + bi.x;
                float o3 = acc[mt][nt][3] + bi.y;
                if (FUSE) {
                    float2 xs = *(const float2*)(xsrc + (size_t)r1g * 256 + c);
                    o2 = sa * o2 + (1.0f - sa) * xs.x;
                    o3 = sa * o3 + (1.0f - sa) * xs.y;
                }
                *(float2*)(C + (size_t)r1g * 256 + c) = make_float2(o2, o3);
            }
        }
    }
}

// 256-thread exclusive scan of g_cur4[ty] -> g_off4[ty]; cur := offset
__device__ void csr_scan_body(int ty) {
    int Nd = (ty == 2) ? NMM : NOP;
    __shared__ int sp[256];
    int tid = threadIdx.x;
    int chunk = (Nd + 255) / 256;
    int beg = tid * chunk;
    int end = beg + chunk; if (end > Nd) end = Nd;
    int s = 0;
    for (int i = beg; i < end; i++) s += g_cur4[ty][i];
    sp[tid] = s;
    __syncthreads();
    #pragma unroll
    for (int o = 1; o < 256; o <<= 1) {
        int v = (tid >= o) ? sp[tid - o] : 0;
        __syncthreads();
        sp[tid] += v;
        __syncthreads();
    }
    int base = (tid == 0) ? 0 : sp[tid - 1];
    for (int i = beg; i < end; i++) {
        int d = g_cur4[ty][i];
        g_off4[ty][i] = base;
        g_cur4[ty][i] = base;
        base += d;
    }
    if (tid == 255) g_off4[ty][Nd] = sp[255];
}

// ---------------- launch 2: 6 k/q/v GEMMs + 4 CSR scans ----------------
__global__ void __launch_bounds__(256) fused_kqv_scan(
    const float* __restrict__ Aop, const float* __restrict__ Am,
    const float* __restrict__ Wk, const float* __restrict__ Wq, const float* __restrict__ Wv,
    const float* __restrict__ bk, const float* __restrict__ bq, const float* __restrict__ bv,
    float* __restrict__ kop, float* __restrict__ qop, float* __restrict__ vop,
    float* __restrict__ km,  float* __restrict__ qm,  float* __restrict__ vm)
{
    int b = blockIdx.x;
    if (b < 3 * TILES_ALL) {
        int z = b / TILES_ALL;
        int t = b % TILES_ALL;
        bool isM = t >= TILES_OP;
        int tt = isM ? t - TILES_OP : t;
        int rowBase = (tt >> 1) * 128;
        int colBase = (tt & 1) * 128;

        const float* A = isM ? Am : Aop;
        int N = isM ? NMM : NOP;
        const float* W = (z == 0 ? Wk : z == 1 ? Wq : Wv) + (isM ? DD * DD : 0);
        const float* bb = (z == 0 ? bk : z == 1 ? bq : bv) + (isM ? DD : 0);
        float* C = isM ? (z == 0 ? km : z == 1 ? qm : vm)
                       : (z == 0 ? kop : z == 1 ? qop : vop);
        gemm_tile_tc<false>(A, W, bb, C, N, nullptr, 0.0f, rowBase, colBase);
    } else {
        csr_scan_body(b - 3 * TILES_ALL);
    }
}

// ---------------- tensor-core rel transform: [64 x 32] @ [32 x 32] per (e,h) block ----------------
// K̃[n,f] = sum_d k[n,h*32+d] * a_rel[e,h,d,f]  (B loaded transposed: Bsmem[f][d])
__device__ void rel_body_tc(int e, int h, int xb,
                            const float* __restrict__ arel,
                            const float* __restrict__ mrel)
{
    int N = (e == 3) ? NMM : NOP;
    int nBase = xb * 64;
    if (nBase >= N) return;

    const float* ktab = (e == 3) ? g_k_m : g_k_op;
    const float* vtab = (e == 3) ? g_v_m : g_v_op;
    float* KT = (e == 3) ? g_KTm : g_KT[e];
    float* VT = (e == 3) ? g_VTm : g_VT[e];

    __shared__ uint32_t Ah[64 * 36], Al[64 * 36];
    __shared__ uint32_t Bah[32 * 36], Bal[32 * 36], Bmh[32 * 36], Bml[32 * 36];

    int tid = threadIdx.x, lane = tid & 31, wid = tid >> 5;
    int grp = lane >> 2, tid4 = lane & 3;
    int mt = wid & 3;             // m-tile (16 rows) within 64
    int ntbase = (wid >> 2) * 2;  // 2 n-tiles of 8 per warp

    // load both relation matrices (transposed) with hi/lo split
    for (int i = tid; i < 1024; i += 256) {
        int d = i >> 5, f = i & 31;
        float va = arel[((size_t)(e * HH + h)) * 1024 + i];
        float vm = mrel[((size_t)(e * HH + h)) * 1024 + i];
        uint32_t hh = cvt_tf32(va);
        Bah[f * 36 + d] = hh;
        Bal[f * 36 + d] = cvt_tf32(va - __uint_as_float(hh));
        hh = cvt_tf32(vm);
        Bmh[f * 36 + d] = hh;
        Bml[f * 36 + d] = cvt_tf32(vm - __uint_as_float(hh));
    }

    #pragma unroll
    for (int phase = 0; phase < 2; phase++) {
        const float* xt = phase ? vtab : ktab;
        __syncthreads();   // phase0: B stores done; phase1: prior mma reads done before A overwrite
        for (int q = tid; q < 512; q += 256) {
            int r = q >> 3, c4 = (q & 7) * 4;
            float4 v = make_float4(0.f, 0.f, 0.f, 0.f);
            if (nBase + r < N)
                v = *(const float4*)(xt + (size_t)(nBase + r) * 256 + h * 32 + c4);
            uint32_t h0 = cvt_tf32(v.x), h1 = cvt_tf32(v.y), h2 = cvt_tf32(v.z), h3 = cvt_tf32(v.w);
            int idx = r * 36 + c4;
            Ah[idx] = h0; Ah[idx + 1] = h1; Ah[idx + 2] = h2; Ah[idx + 3] = h3;
            Al[idx]     = cvt_tf32(v.x - __uint_as_float(h0));
            Al[idx + 1] = cvt_tf32(v.y - __uint_as_float(h1));
            Al[idx + 2] = cvt_tf32(v.z - __uint_as_float(h2));
            Al[idx + 3] = cvt_tf32(v.w - __uint_as_float(h3));
        }
        __syncthreads();

        const uint32_t* Bh = phase ? Bmh : Bah;
        const uint32_t* Bl = phase ? Bml : Bal;
        float acc[2][4];
        #pragma unroll
        for (int j = 0; j < 2; j++)
            #pragma unroll
            for (int r = 0; r < 4; r++) acc[j][r] = 0.0f;

        #pragma unroll
        for (int kc = 0; kc < 4; kc++) {
            int kb = kc * 8 + tid4;
            int ab = (mt * 16 + grp) * 36 + kb;
            uint32_t ah[4] = {Ah[ab], Ah[ab + 8 * 36], Ah[ab + 4], Ah[ab + 8 * 36 + 4]};
            uint32_t al[4] = {Al[ab], Al[ab + 8 * 36], Al[ab + 4], Al[ab + 8 * 36 + 4]};
            #pragma unroll
            for (int j = 0; j < 2; j++) {
                int bb = ((ntbase + j) * 8 + grp) * 36 + kb;
                uint32_t bh[2] = {Bh[bb], Bh[bb + 4]};
                uint32_t bl[2] = {Bl[bb], Bl[bb + 4]};
                mma_tf32(acc[j], ah, bh);
                mma_tf32(acc[j], ah, bl);
                mma_tf32(acc[j], al, bh);
            }
        }

        float* OUT = phase ? VT : KT;
        int r0 = nBase + mt * 16 + grp;
        int r1 = r0 + 8;
        #pragma unroll
        for (int j = 0; j < 2; j++) {
            int c = (ntbase + j) * 8 + tid4 * 2;
            if (r0 < N)
                *(float2*)(OUT + (size_t)r0 * 256 + h * 32 + c) = make_float2(acc[j][0], acc[j][1]);
            if (r1 < N)
                *(float2*)(OUT + (size_t)r1 * 256 + h * 32 + c) = make_float2(acc[j][2], acc[j][3]);
        }
    }
}

// ---------------- launch 3: rel transforms (TC) + CSR fill ----------------
__global__ void __launch_bounds__(256) fused_rel_fill(
    const float* __restrict__ arel, const float* __restrict__ mrel,
    const int* __restrict__ e0, const int* __restrict__ e1,
    const int* __restrict__ e2, const int* __restrict__ e3)
{
    int b = blockIdx.x;
    if (b < 3 * RELB_OP) {
        int e = b / RELB_OP;
        int rem = b % RELB_OP;
        int h = rem / RELB_PER_H;
        int xb = rem % RELB_PER_H;
        rel_body_tc(e, h, xb, arel, mrel);
    } else if (b < REL_TC) {
        int b2 = b - 3 * RELB_OP;
        int h = b2 / RELB_M_PER_H;
        int xb = b2 % RELB_M_PER_H;
        rel_body_tc(3, h, xb, arel, mrel);
    } else {
        int cb = b - REL_TC;
        int ty = cb / CNT_BPT;
        int i = (cb % CNT_BPT) * 256 + threadIdx.x;
        if (i < EE) {
            const int* ei = (ty == 0) ? e0 : (ty == 1) ? e1 : (ty == 2) ? e2 : e3;
            int dst = ei[EE + i];
            int src = ei[i];
            int pos = atomicAdd(&g_cur4[ty][dst], 1);
            g_esrc4[ty][pos] = src;
        }
    }
}

// ---------------- gather bodies ----------------
__device__ void gather_op_body(int b, const float* __restrict__ prel)
{
    int w = b * 8 + (threadIdx.x >> 5);
    int lane = threadIdx.x & 31;
    if (w >= NOP) return;

    const float4* qp = (const float4*)(g_q_op + (size_t)w * 256);
    float4 q0 = qp[lane * 2], q1 = qp[lane * 2 + 1];
    int h = lane >> 2;

    float out[8] = {0.f, 0.f, 0.f, 0.f, 0.f, 0.f, 0.f, 0.f};

    #pragma unroll
    for (int pass = 0; pass < 3; pass++) {
        int e = (pass == 2) ? 3 : pass;
        const float* KT = (pass == 2) ? g_KTm : g_KT[e];
        const float* VT = (pass == 2) ? g_VTm : g_VT[e];
        float ps = prel[e * HH + h] * 0.17677669529663687f;   // 1/sqrt(32)

        int beg = g_off4[e][w], end = g_off4[e][w + 1];
        float num[8] = {0.f, 0.f, 0.f, 0.f, 0.f, 0.f, 0.f, 0.f};
        float den = 0.0f;
        #pragma unroll 2
        for (int j = beg; j < end; j++) {
            int src = g_esrc4[e][j];
            const float4* kp = (const float4*)(KT + (size_t)src * 256);
            const float4* vp = (const float4*)(VT + (size_t)src * 256);
            float4 k0 = kp[lane * 2], k1 = kp[lane * 2 + 1];
            float4 v0 = vp[lane * 2], v1 = vp[lane * 2 + 1];
            float s = q0.x * k0.x + q0.y * k0.y + q0.z * k0.z + q0.w * k0.w
                    + q1.x * k1.x + q1.y * k1.y + q1.z * k1.z + q1.w * k1.w;
            s += __shfl_xor_sync(0xffffffffu, s, 1);
            s += __shfl_xor_sync(0xffffffffu, s, 2);
            float ev = expf(s * ps);
            den += ev;
            num[0] += ev * v0.x; num[1] += ev * v0.y; num[2] += ev * v0.z; num[3] += ev * v0.w;
            num[4] += ev * v1.x; num[5] += ev * v1.y; num[6] += ev * v1.z; num[7] += ev * v1.w;
        }
        float inv = (den > 0.f) ? 1.0f / den : 0.0f;
        #pragma unroll
        for (int i = 0; i < 8; i++) out[i] += num[i] * inv;
    }

    float* ap = g_acc_op + (size_t)w * 256 + lane * 8;
    *(float4*)(ap)     = make_float4(out[0], out[1], out[2], out[3]);
    *(float4*)(ap + 4) = make_float4(out[4], out[5], out[6], out[7]);
}

__device__ void gather_m_body(int n, const float* __restrict__ prel)
{
    __shared__ float snum[8][256];
    __shared__ float sden[8][8];
    int warp = threadIdx.x >> 5, lane = threadIdx.x & 31;
    int h = lane >> 2;
    int beg = g_off4[2][n], end = g_off4[2][n + 1];

    const float4* qp = (const float4*)(g_q_m + (size_t)n * 256);
    float4 q0 = qp[lane * 2], q1 = qp[lane * 2 + 1];
    float ps = prel[2 * HH + h] * 0.17677669529663687f;

    float num[8] = {0.f, 0.f, 0.f, 0.f, 0.f, 0.f, 0.f, 0.f};
    float den = 0.0f;

    for (int j = beg + warp; j < end; j += 8) {
        int src = g_esrc4[2][j];
        const float4* kp = (const float4*)(g_KT[2] + (size_t)src * 256);
        const float4* vp = (const float4*)(g_VT[2] + (size_t)src * 256);
        float4 k0 = kp[lane * 2], k1 = kp[lane * 2 + 1];
        float4 v0 = vp[lane * 2], v1 = vp[lane * 2 + 1];
        float s = q0.x * k0.x + q0.y * k0.y + q0.z * k0.z + q0.w * k0.w
                + q1.x * k1.x + q1.y * k1.y + q1.z * k1.z + q1.w * k1.w;
        s += __shfl_xor_sync(0xffffffffu, s, 1);
        s += __shfl_xor_sync(0xffffffffu, s, 2);
        float ev = expf(s * ps);
        den += ev;
        num[0] += ev * v0.x; num[1] += ev * v0.y; num[2] += ev * v0.z; num[3] += ev * v0.w;
        num[4] += ev * v1.x; num[5] += ev * v1.y; num[6] += ev * v1.z; num[7] += ev * v1.w;
    }
    #pragma unroll
    for (int i = 0; i < 8; i += 4)
        *(float4*)&snum[warp][lane * 8 + i] = make_float4(num[i], num[i+1], num[i+2], num[i+3]);
    if ((lane & 3) == 0) sden[warp][h] = den;
    __syncthreads();

    {
        int c = threadIdx.x;
        float tot = 0.0f;
        #pragma unroll
        for (int ww = 0; ww < 8; ww++) tot += snum[ww][c];
        int hh = c >> 5;
        float d = 0.0f;
        #pragma unroll
        for (int ww = 0; ww < 8; ww++) d += sden[ww][hh];
        g_acc_m[(size_t)n * 256 + c] = (d > 0.f) ? tot / d : 0.0f;
    }
}

// ---------------- launch 4: both gathers ----------------
__global__ void __launch_bounds__(256) fused_gather(const float* __restrict__ prel)
{
    int b = blockIdx.x;
    if (b < GOP_BLOCKS) gather_op_body(b, prel);
    else                gather_m_body(b - GOP_BLOCKS, prel);
}

// ---------------- launch 5: both final FUSE GEMMs ----------------
__global__ void __launch_bounds__(256) gemm_final(
    const float* __restrict__ accop, const float* __restrict__ accm,
    const float* __restrict__ Wa, const float* __restrict__ ba,
    const float* __restrict__ xop, const float* __restrict__ xm,
    const float* __restrict__ skipv, float* __restrict__ out)
{
    int t = blockIdx.x;
    bool isM = t >= TILES_OP;
    int tt = isM ? t - TILES_OP : t;
    int rowBase = (tt >> 1) * 128;
    int colBase = (tt & 1) * 128;

    const float* A = isM ? accm : accop;
    int N = isM ? NMM : NOP;
    const float* W = Wa + (isM ? DD * DD : 0);
    const float* b = ba + (isM ? DD : 0);
    const float* xs = isM ? xm : xop;
    float* C = out + (isM ? (size_t)NOP * DD : 0);
    float sa = 1.0f / (1.0f + expf(-skipv[isM ? 1 : 0]));

    gemm_tile_tc<true>(A, W, b, C, N, xs, sa, rowBase, colBase);
}

// ---------------- host side ----------------
static float* symaddr(const void* sym) {
    void* p = nullptr;
    cudaGetSymbolAddress(&p, sym);
    return (float*)p;
}

extern "C" void kernel_launch(void* const* d_in, const int* in_sizes, int n_in,
                              void* d_out, int out_size)
{
    const float* x_op    = (const float*)d_in[0];
    const float* x_m     = (const float*)d_in[1];
    const float* delta_t = (const float*)d_in[2];
    const int*   ei0 = (const int*)d_in[3];
    const int*   ei1 = (const int*)d_in[4];
    const int*   ei2 = (const int*)d_in[5];
    const int*   ei3 = (const int*)d_in[6];
    const float* Wt   = (const float*)d_in[7];
    const float* bt   = (const float*)d_in[8];
    const float* ln_g = (const float*)d_in[9];
    const float* ln_b = (const float*)d_in[10];
    const float* Wk   = (const float*)d_in[11];
    const float* bk   = (const float*)d_in[12];
    const float* Wq   = (const float*)d_in[13];
    const float* bq   = (const float*)d_in[14];
    const float* Wv   = (const float*)d_in[15];
    const float* bv   = (const float*)d_in[16];
    const float* Wa   = (const float*)d_in[17];
    const float* ba   = (const float*)d_in[18];
    const float* skip = (const float*)d_in[19];
    const float* a_rel = (const float*)d_in[20];
    const float* m_rel = (const float*)d_in[21];
    const float* p_rel = (const float*)d_in[22];
    float* out = (float*)d_out;

    float* xw    = symaddr(g_xw);
    float* k_op  = symaddr(g_k_op);
    float* q_op  = symaddr(g_q_op);
    float* v_op  = symaddr(g_v_op);
    float* k_m   = symaddr(g_k_m);
    float* q_m   = symaddr(g_q_m);
    float* v_m   = symaddr(g_v_m);
    float* acc_op = symaddr(g_acc_op);
    float* acc_m  = symaddr(g_acc_m);
    int*   cur4  = (int*)symaddr(g_cur4);

    cudaMemcpyAsync(xw, x_op, (size_t)NOP * DD * sizeof(float), cudaMemcpyDeviceToDevice);
    cudaMemsetAsync(cur4, 0, (size_t)4 * NOP * sizeof(int));

    // L1: temporal encoding + CSR degree count
    fused_temporal_count<<<TEMP_BLOCKS + 4 * CNT_BPT, 256>>>(
        delta_t, ei0, ei1, ei2, ei3, Wt, bt, ln_g, ln_b);

    // L2: 6 k/q/v GEMMs (pipelined 3xTF32) + 4 CSR scans
    fused_kqv_scan<<<3 * TILES_ALL + 4, 256>>>(
        xw, x_m, Wk, Wq, Wv, bk, bq, bv,
        k_op, q_op, v_op, k_m, q_m, v_m);

    // L3: relation transforms (tensor core) + CSR fill
    fused_rel_fill<<<REL_TC + 4 * CNT_BPT, 256>>>(a_rel, m_rel, ei0, ei1, ei2, ei3);

    // L4: both gathers
    fused_gather<<<GOP_BLOCKS + NMM, 256>>>(p_rel);

    // L5: both final GEMMs (tensor core)
    gemm_final<<<TILES_ALL, 256>>>(acc_op, acc_m, Wa, ba, xw, x_m, skip, out);
}

// round 15
// speedup vs baseline: 1.0402x; 1.0402x over previous
#include <cuda_runtime.h>
#include <math.h>
#include <stdint.h>

#define NOP 20000
#define NMM 500
#define DD  256
#define HH  8
#define DHD 32
#define TDE 16
#define EE  200000

#define TILES_OP 314   // 157 rowblocks x 2 colblocks
#define TILES_M  8     // 4 x 2
#define TILES_ALL (TILES_OP + TILES_M)

#define TEMP_BLOCKS 782            // ceil(EE/256), 256 edges per block
#define CNT_BPT 782                // count blocks per edge type: ceil(EE/256)
#define RELB_PER_H 313             // ceil(NOP/64) node-blocks per (type<3, head)
#define RELB_OP (RELB_PER_H * HH)  // 2504 per op-src type
#define RELB_M_PER_H 8             // ceil(NMM/64)
#define REL_TC (3 * RELB_OP + RELB_M_PER_H * HH)   // 7576
#define GOP_BLOCKS 2500            // NOP*32/256

#define SMP 20
#define PIECE (128 * SMP)          // 2560 u32 per matrix piece
#define BUFU32 (4 * PIECE)         // Ah|Al|Bh|Bl = 10240 u32 per buffer
#define DYN_BYTES (2 * BUFU32 * 4) // 81920 bytes

// ---------------- scratch ----------------
__device__ float g_xw[NOP * DD];
__device__ float g_k_op[NOP * DD];
__device__ float g_q_op[NOP * DD];
__device__ float g_v_op[NOP * DD];
__device__ float g_k_m[NMM * DD];
__device__ float g_q_m[NMM * DD];
__device__ float g_v_m[NMM * DD];
__device__ float g_KT[3][NOP * DD];
__device__ float g_VT[3][NOP * DD];
__device__ float g_KTm[NMM * DD];
__device__ float g_VTm[NMM * DD];
__device__ float g_acc_op[NOP * DD];
__device__ float g_acc_m[NMM * DD];
__device__ int   g_off4[4][NOP + 1];
__device__ int   g_cur4[4][NOP];
__device__ int   g_esrc4[4][EE];

__device__ __forceinline__ float gelu_exact(float x) {
    return 0.5f * x * (1.0f + erff(x * 0.70710678118654752f));
}

__device__ __forceinline__ void red_add_v4(float* p, float a, float b, float c, float d) {
    asm volatile("red.global.add.v4.f32 [%0], {%1, %2, %3, %4};"
                 :: "l"(p), "f"(a), "f"(b), "f"(c), "f"(d) : "memory");
}

__device__ __forceinline__ uint32_t cvt_tf32(float x) {
    uint32_t r; asm("cvt.rna.tf32.f32 %0, %1;" : "=r"(r) : "f"(x)); return r;
}

__device__ __forceinline__ void mma_tf32(float* c, const uint32_t* a, const uint32_t* b) {
    asm volatile("mma.sync.aligned.m16n8k8.row.col.f32.tf32.tf32.f32 "
                 "{%0,%1,%2,%3}, {%4,%5,%6,%7}, {%8,%9}, {%0,%1,%2,%3};"
                 : "+f"(c[0]), "+f"(c[1]), "+f"(c[2]), "+f"(c[3])
                 : "r"(a[0]), "r"(a[1]), "r"(a[2]), "r"(a[3]),
                   "r"(b[0]), "r"(b[1]));
}

// ---------------- temporal encoding: 256 edges per block, 8 warps x 32 edges ----------------
__device__ void temporal_body(int blk,
                              const float* __restrict__ delta_t,
                              const int* __restrict__ ei_src,
                              const float* __restrict__ Wt,
                              const float* __restrict__ bt,
                              const float* __restrict__ ln_g,
                              const float* __restrict__ ln_b)
{
    __shared__ float Wts[TDE * DD];
    __shared__ float bts[DD], gs[DD], bs[DD];
    __shared__ float tr[8][DD];
    for (int idx = threadIdx.x; idx < DD * TDE; idx += blockDim.x) {
        int j = idx / TDE, i = idx % TDE;
        Wts[i * DD + j] = Wt[idx];
    }
    for (int idx = threadIdx.x; idx < DD; idx += blockDim.x) {
        bts[idx] = bt[idx]; gs[idx] = ln_g[idx]; bs[idx] = ln_b[idx];
    }
    __syncthreads();

    int warp = threadIdx.x >> 5;
    int lane = threadIdx.x & 31;

    float freqs[8];
    #pragma unroll
    for (int m = 0; m < 8; m++)
        freqs[m] = exp2f(-(float)m * (9.965784284662087f / 8.0f));  // 1000^{-m/8}

    #pragma unroll 1
    for (int t = 0; t < 32; t++) {
        int w = blk * 256 + warp * 32 + t;
        if (w >= EE) break;

        float dt = delta_t[w];
        int src = ei_src[w];

        float sn[8], cn[8];
        #pragma unroll
        for (int m = 0; m < 8; m++) sincosf(dt * freqs[m], &sn[m], &cn[m]);

        float pt[8];
        float lsum = 0.0f;
        #pragma unroll
        for (int jj = 0; jj < 8; jj++) {
            int j = lane + jj * 32;
            float s = bts[j];
            #pragma unroll
            for (int m = 0; m < 8; m++)
                s += sn[m] * Wts[(2 * m) * DD + j] + cn[m] * Wts[(2 * m + 1) * DD + j];
            pt[jj] = s;
            lsum += s;
        }
        #pragma unroll
        for (int o = 16; o; o >>= 1) lsum += __shfl_xor_sync(0xffffffffu, lsum, o);
        float mu = lsum * (1.0f / 256.0f);

        float lvar = 0.0f;
        #pragma unroll
        for (int jj = 0; jj < 8; jj++) { float d = pt[jj] - mu; lvar += d * d; }
        #pragma unroll
        for (int o = 16; o; o >>= 1) lvar += __shfl_xor_sync(0xffffffffu, lvar, o);
        float rstd = rsqrtf(lvar * (1.0f / 256.0f) + 1e-5f);

        #pragma unroll
        for (int jj = 0; jj < 8; jj++) {
            int j = lane + jj * 32;
            tr[warp][j] = (pt[jj] - mu) * rstd * gs[j] + bs[j];
        }
        __syncwarp();
        float4 y0 = *(const float4*)&tr[warp][lane * 8];
        float4 y1 = *(const float4*)&tr[warp][lane * 8 + 4];
        float* xp = &g_xw[(size_t)src * DD + lane * 8];
        red_add_v4(xp,     y0.x, y0.y, y0.z, y0.w);
        red_add_v4(xp + 4, y1.x, y1.y, y1.z, y1.w);
        __syncwarp();
    }
}

// ---------------- launch 1: temporal + CSR count ----------------
__global__ void __launch_bounds__(256) fused_temporal_count(
    const float* __restrict__ delta_t,
    const int* __restrict__ e0, const int* __restrict__ e1,
    const int* __restrict__ e2, const int* __restrict__ e3,
    const float* __restrict__ Wt, const float* __restrict__ bt,
    const float* __restrict__ ln_g, const float* __restrict__ ln_b)
{
    int b = blockIdx.x;
    if (b < TEMP_BLOCKS) {
        temporal_body(b, delta_t, e0, Wt, bt, ln_g, ln_b);
    } else {
        int cb = b - TEMP_BLOCKS;
        int ty = cb / CNT_BPT;
        int i = (cb % CNT_BPT) * 256 + threadIdx.x;
        if (i < EE) {
            const int* ei = (ty == 0) ? e0 : (ty == 1) ? e1 : (ty == 2) ? e2 : e3;
            atomicAdd(&g_cur4[ty][ei[EE + i]], 1);
        }
    }
}

// ---------------- tensor-core 3xTF32 GEMM tile: 128x128, K=256, double-buffered (1 sync/iter) ----------------
__device__ __forceinline__ void split_store(uint32_t* H, uint32_t* L, int idx, float4 v) {
    uint32_t h0 = cvt_tf32(v.x), h1 = cvt_tf32(v.y), h2 = cvt_tf32(v.z), h3 = cvt_tf32(v.w);
    uint32_t l0 = cvt_tf32(v.x - __uint_as_float(h0));
    uint32_t l1 = cvt_tf32(v.y - __uint_as_float(h1));
    uint32_t l2 = cvt_tf32(v.z - __uint_as_float(h2));
    uint32_t l3 = cvt_tf32(v.w - __uint_as_float(h3));
    *(uint4*)&H[idx] = make_uint4(h0, h1, h2, h3);
    *(uint4*)&L[idx] = make_uint4(l0, l1, l2, l3);
}

template <bool FUSE>
__device__ __forceinline__ void gemm_tile_tc(
    uint32_t* smem,
    const float* __restrict__ A, const float* __restrict__ W,
    const float* __restrict__ bias, float* __restrict__ C, int N,
    const float* __restrict__ xsrc, float sa, int rowBase, int colBase)
{
    int tid = threadIdx.x;
    int lane = tid & 31;
    int wid = tid >> 5;
    int mwarp = wid >> 2;
    int nwarp = wid & 3;
    int grp  = lane >> 2;
    int tid4 = lane & 3;

    int row0 = tid >> 2, q0 = (tid & 3) * 4;
    int row1 = row0 + 64;
    int gr0 = rowBase + row0, gr1 = rowBase + row1;
    int gc0 = colBase + row0, gc1 = colBase + row1;

    float acc[4][4][4];
    #pragma unroll
    for (int i = 0; i < 4; i++)
        #pragma unroll
        for (int j = 0; j < 4; j++)
            #pragma unroll
            for (int r = 0; r < 4; r++) acc[i][j][r] = 0.0f;

    float4 av0, av1, bv0, bv1;
    auto ldg = [&](int kt) {
        av0 = make_float4(0.f, 0.f, 0.f, 0.f);
        av1 = make_float4(0.f, 0.f, 0.f, 0.f);
        if (gr0 < N) av0 = *(const float4*)(A + (size_t)gr0 * 256 + kt + q0);
        if (gr1 < N) av1 = *(const float4*)(A + (size_t)gr1 * 256 + kt + q0);
        if (FUSE) {
            av0.x = gelu_exact(av0.x); av0.y = gelu_exact(av0.y);
            av0.z = gelu_exact(av0.z); av0.w = gelu_exact(av0.w);
            av1.x = gelu_exact(av1.x); av1.y = gelu_exact(av1.y);
            av1.z = gelu_exact(av1.z); av1.w = gelu_exact(av1.w);
        }
        bv0 = *(const float4*)(W + (size_t)gc0 * 256 + kt + q0);
        bv1 = *(const float4*)(W + (size_t)gc1 * 256 + kt + q0);
    };
    auto sts = [&](int buf) {
        uint32_t* Ah = smem + buf * BUFU32;
        uint32_t* Al = Ah + PIECE;
        uint32_t* Bh = Ah + 2 * PIECE;
        uint32_t* Bl = Ah + 3 * PIECE;
        split_store(Ah, Al, row0 * SMP + q0, av0);
        split_store(Ah, Al, row1 * SMP + q0, av1);
        split_store(Bh, Bl, row0 * SMP + q0, bv0);
        split_store(Bh, Bl, row1 * SMP + q0, bv1);
    };

    ldg(0);
    sts(0);

    for (int it = 0; it < 16; it++) {
        __syncthreads();
        if (it < 15) ldg((it + 1) * 16);

        const uint32_t* Ah = smem + (it & 1) * BUFU32;
        const uint32_t* Al = Ah + PIECE;
        const uint32_t* Bh = Ah + 2 * PIECE;
        const uint32_t* Bl = Ah + 3 * PIECE;

        #pragma unroll
        for (int s = 0; s < 2; s++) {
            int kb = s * 8 + tid4;
            uint32_t ah[4][4], al[4][4];
            #pragma unroll
            for (int mt = 0; mt < 4; mt++) {
                int base = (mwarp * 64 + mt * 16 + grp) * SMP + kb;
                ah[mt][0] = Ah[base];            al[mt][0] = Al[base];
                ah[mt][1] = Ah[base + 8 * SMP];  al[mt][1] = Al[base + 8 * SMP];
                ah[mt][2] = Ah[base + 4];        al[mt][2] = Al[base + 4];
                ah[mt][3] = Ah[base + 8 * SMP + 4]; al[mt][3] = Al[base + 8 * SMP + 4];
            }
            uint32_t bh[4][2], bl[4][2];
            #pragma unroll
            for (int nt = 0; nt < 4; nt++) {
                int base = (nwarp * 32 + nt * 8 + grp) * SMP + kb;
                bh[nt][0] = Bh[base];     bl[nt][0] = Bl[base];
                bh[nt][1] = Bh[base + 4]; bl[nt][1] = Bl[base + 4];
            }
            #pragma unroll
            for (int mt = 0; mt < 4; mt++)
                #pragma unroll
                for (int nt = 0; nt < 4; nt++) {
                    mma_tf32(acc[mt][nt], ah[mt], bh[nt]);
                    mma_tf32(acc[mt][nt], ah[mt], bl[nt]);
                    mma_tf32(acc[mt][nt], al[mt], bh[nt]);
                }
        }
        if (it < 15) sts((it + 1) & 1);   // writes the buffer NOT being read this iter
    }

    #pragma unroll
    for (int mt = 0; mt < 4; mt++) {
        int r0g = rowBase + mwarp * 64 + mt * 16 + grp;
        int r1g = r0g + 8;
        #pragma unroll
        for (int nt = 0; nt < 4; nt++) {
            int c = colBase + nwarp * 32 + nt * 8 + tid4 * 2;
            float2 bi = *(const float2*)(bias + c);
            if (r0g < N) {
                float o0 = acc[mt][nt][0] + bi.x;
                float o1 = acc[mt][nt][1] + bi.y;
                if (FUSE) {
                    float2 xs = *(const float2*)(xsrc + (size_t)r0g * 256 + c);
                    o0 = sa * o0 + (1.0f - sa) * xs.x;
                    o1 = sa * o1 + (1.0f - sa) * xs.y;
                }
                *(float2*)(C + (size_t)r0g * 256 + c) = make_float2(o0, o1);
            }
            if (r1g < N) {
                float o2 = acc[mt][nt][2] + bi.x;
                float o3 = acc[mt][nt][3] + bi.y;
                if (FUSE) {
                    float2 xs = *(const float2*)(xsrc + (size_t)r1g * 256 + c);
                    o2 = sa * o2 + (1.0f - sa) * xs.x;
                    o3 = sa * o3 + (1.0f - sa) * xs.y;
                }
                *(float2*)(C + (size_t)r1g * 256 + c) = make_float2(o2, o3);
            }
        }
    }
}

// 256-thread exclusive scan of g_cur4[ty] -> g_off4[ty]; cur := offset
__device__ void csr_scan_body(int ty) {
    int Nd = (ty == 2) ? NMM : NOP;
    __shared__ int sp[256];
    int tid = threadIdx.x;
    int chunk = (Nd + 255) / 256;
    int beg = tid * chunk;
    int end = beg + chunk; if (end > Nd) end = Nd;
    int s = 0;
    for (int i = beg; i < end; i++) s += g_cur4[ty][i];
    sp[tid] = s;
    __syncthreads();
    #pragma unroll
    for (int o = 1; o < 256; o <<= 1) {
        int v = (tid >= o) ? sp[tid - o] : 0;
        __syncthreads();
        sp[tid] += v;
        __syncthreads();
    }
    int base = (tid == 0) ? 0 : sp[tid - 1];
    for (int i = beg; i < end; i++) {
        int d = g_cur4[ty][i];
        g_off4[ty][i] = base;
        g_cur4[ty][i] = base;
        base += d;
    }
    if (tid == 255) g_off4[ty][Nd] = sp[255];
}

// ---------------- launch 2: 6 k/q/v GEMMs + 4 CSR scans ----------------
__global__ void __launch_bounds__(256, 2) fused_kqv_scan(
    const float* __restrict__ Aop, const float* __restrict__ Am,
    const float* __restrict__ Wk, const float* __restrict__ Wq, const float* __restrict__ Wv,
    const float* __restrict__ bk, const float* __restrict__ bq, const float* __restrict__ bv,
    float* __restrict__ kop, float* __restrict__ qop, float* __restrict__ vop,
    float* __restrict__ km,  float* __restrict__ qm,  float* __restrict__ vm)
{
    extern __shared__ uint32_t dynsmem[];
    int b = blockIdx.x;
    if (b < 3 * TILES_ALL) {
        int z = b / TILES_ALL;
        int t = b % TILES_ALL;
        bool isM = t >= TILES_OP;
        int tt = isM ? t - TILES_OP : t;
        int rowBase = (tt >> 1) * 128;
        int colBase = (tt & 1) * 128;

        const float* A = isM ? Am : Aop;
        int N = isM ? NMM : NOP;
        const float* W = (z == 0 ? Wk : z == 1 ? Wq : Wv) + (isM ? DD * DD : 0);
        const float* bb = (z == 0 ? bk : z == 1 ? bq : bv) + (isM ? DD : 0);
        float* C = isM ? (z == 0 ? km : z == 1 ? qm : vm)
                       : (z == 0 ? kop : z == 1 ? qop : vop);
        gemm_tile_tc<false>(dynsmem, A, W, bb, C, N, nullptr, 0.0f, rowBase, colBase);
    } else {
        csr_scan_body(b - 3 * TILES_ALL);
    }
}

// ---------------- tensor-core rel transform: [64 x 32] @ [32 x 32] per (e,h) block ----------------
__device__ void rel_body_tc(int e, int h, int xb,
                            const float* __restrict__ arel,
                            const float* __restrict__ mrel)
{
    int N = (e == 3) ? NMM : NOP;
    int nBase = xb * 64;
    if (nBase >= N) return;

    const float* ktab = (e == 3) ? g_k_m : g_k_op;
    const float* vtab = (e == 3) ? g_v_m : g_v_op;
    float* KT = (e == 3) ? g_KTm : g_KT[e];
    float* VT = (e == 3) ? g_VTm : g_VT[e];

    __shared__ uint32_t Ah[64 * 36], Al[64 * 36];
    __shared__ uint32_t Bah[32 * 36], Bal[32 * 36], Bmh[32 * 36], Bml[32 * 36];

    int tid = threadIdx.x, lane = tid & 31, wid = tid >> 5;
    int grp = lane >> 2, tid4 = lane & 3;
    int mt = wid & 3;
    int ntbase = (wid >> 2) * 2;

    for (int i = tid; i < 1024; i += 256) {
        int d = i >> 5, f = i & 31;
        float va = arel[((size_t)(e * HH + h)) * 1024 + i];
        float vm = mrel[((size_t)(e * HH + h)) * 1024 + i];
        uint32_t hh = cvt_tf32(va);
        Bah[f * 36 + d] = hh;
        Bal[f * 36 + d] = cvt_tf32(va - __uint_as_float(hh));
        hh = cvt_tf32(vm);
        Bmh[f * 36 + d] = hh;
        Bml[f * 36 + d] = cvt_tf32(vm - __uint_as_float(hh));
    }

    #pragma unroll
    for (int phase = 0; phase < 2; phase++) {
        const float* xt = phase ? vtab : ktab;
        __syncthreads();
        for (int q = tid; q < 512; q += 256) {
            int r = q >> 3, c4 = (q & 7) * 4;
            float4 v = make_float4(0.f, 0.f, 0.f, 0.f);
            if (nBase + r < N)
                v = *(const float4*)(xt + (size_t)(nBase + r) * 256 + h * 32 + c4);
            uint32_t h0 = cvt_tf32(v.x), h1 = cvt_tf32(v.y), h2 = cvt_tf32(v.z), h3 = cvt_tf32(v.w);
            int idx = r * 36 + c4;
            Ah[idx] = h0; Ah[idx + 1] = h1; Ah[idx + 2] = h2; Ah[idx + 3] = h3;
            Al[idx]     = cvt_tf32(v.x - __uint_as_float(h0));
            Al[idx + 1] = cvt_tf32(v.y - __uint_as_float(h1));
            Al[idx + 2] = cvt_tf32(v.z - __uint_as_float(h2));
            Al[idx + 3] = cvt_tf32(v.w - __uint_as_float(h3));
        }
        __syncthreads();

        const uint32_t* Bh = phase ? Bmh : Bah;
        const uint32_t* Bl = phase ? Bml : Bal;
        float acc[2][4];
        #pragma unroll
        for (int j = 0; j < 2; j++)
            #pragma unroll
            for (int r = 0; r < 4; r++) acc[j][r] = 0.0f;

        #pragma unroll
        for (int kc = 0; kc < 4; kc++) {
            int kb = kc * 8 + tid4;
            int ab = (mt * 16 + grp) * 36 + kb;
            uint32_t ah[4] = {Ah[ab], Ah[ab + 8 * 36], Ah[ab + 4], Ah[ab + 8 * 36 + 4]};
            uint32_t al[4] = {Al[ab], Al[ab + 8 * 36], Al[ab + 4], Al[ab + 8 * 36 + 4]};
            #pragma unroll
            for (int j = 0; j < 2; j++) {
                int bb = ((ntbase + j) * 8 + grp) * 36 + kb;
                uint32_t bh[2] = {Bh[bb], Bh[bb + 4]};
                uint32_t bl[2] = {Bl[bb], Bl[bb + 4]};
                mma_tf32(acc[j], ah, bh);
                mma_tf32(acc[j], ah, bl);
                mma_tf32(acc[j], al, bh);
            }
        }

        float* OUT = phase ? VT : KT;
        int r0 = nBase + mt * 16 + grp;
        int r1 = r0 + 8;
        #pragma unroll
        for (int j = 0; j < 2; j++) {
            int c = (ntbase + j) * 8 + tid4 * 2;
            if (r0 < N)
                *(float2*)(OUT + (size_t)r0 * 256 + h * 32 + c) = make_float2(acc[j][0], acc[j][1]);
            if (r1 < N)
                *(float2*)(OUT + (size_t)r1 * 256 + h * 32 + c) = make_float2(acc[j][2], acc[j][3]);
        }
    }
}

// ---------------- launch 3: rel transforms (TC) + CSR fill ----------------
__global__ void __launch_bounds__(256) fused_rel_fill(
    const float* __restrict__ arel, const float* __restrict__ mrel,
    const int* __restrict__ e0, const int* __restrict__ e1,
    const int* __restrict__ e2, const int* __restrict__ e3)
{
    int b = blockIdx.x;
    if (b < 3 * RELB_OP) {
        int e = b / RELB_OP;
        int rem = b % RELB_OP;
        int h = rem / RELB_PER_H;
        int xb = rem % RELB_PER_H;
        rel_body_tc(e, h, xb, arel, mrel);
    } else if (b < REL_TC) {
        int b2 = b - 3 * RELB_OP;
        int h = b2 / RELB_M_PER_H;
        int xb = b2 % RELB_M_PER_H;
        rel_body_tc(3, h, xb, arel, mrel);
    } else {
        int cb = b - REL_TC;
        int ty = cb / CNT_BPT;
        int i = (cb % CNT_BPT) * 256 + threadIdx.x;
        if (i < EE) {
            const int* ei = (ty == 0) ? e0 : (ty == 1) ? e1 : (ty == 2) ? e2 : e3;
            int dst = ei[EE + i];
            int src = ei[i];
            int pos = atomicAdd(&g_cur4[ty][dst], 1);
            g_esrc4[ty][pos] = src;
        }
    }
}

// ---------------- gather bodies ----------------
__device__ void gather_op_body(int b, const float* __restrict__ prel)
{
    int w = b * 8 + (threadIdx.x >> 5);
    int lane = threadIdx.x & 31;
    if (w >= NOP) return;

    const float4* qp = (const float4*)(g_q_op + (size_t)w * 256);
    float4 q0 = qp[lane * 2], q1 = qp[lane * 2 + 1];
    int h = lane >> 2;

    float out[8] = {0.f, 0.f, 0.f, 0.f, 0.f, 0.f, 0.f, 0.f};

    #pragma unroll
    for (int pass = 0; pass < 3; pass++) {
        int e = (pass == 2) ? 3 : pass;
        const float* KT = (pass == 2) ? g_KTm : g_KT[e];
        const float* VT = (pass == 2) ? g_VTm : g_VT[e];
        float ps = prel[e * HH + h] * 0.17677669529663687f;   // 1/sqrt(32)

        int beg = g_off4[e][w], end = g_off4[e][w + 1];
        float num[8] = {0.f, 0.f, 0.f, 0.f, 0.f, 0.f, 0.f, 0.f};
        float den = 0.0f;
        #pragma unroll 2
        for (int j = beg; j < end; j++) {
            int src = g_esrc4[e][j];
            const float4* kp = (const float4*)(KT + (size_t)src * 256);
            const float4* vp = (const float4*)(VT + (size_t)src * 256);
            float4 k0 = kp[lane * 2], k1 = kp[lane * 2 + 1];
            float4 v0 = vp[lane * 2], v1 = vp[lane * 2 + 1];
            float s = q0.x * k0.x + q0.y * k0.y + q0.z * k0.z + q0.w * k0.w
                    + q1.x * k1.x + q1.y * k1.y + q1.z * k1.z + q1.w * k1.w;
            s += __shfl_xor_sync(0xffffffffu, s, 1);
            s += __shfl_xor_sync(0xffffffffu, s, 2);
            float ev = expf(s * ps);
            den += ev;
            num[0] += ev * v0.x; num[1] += ev * v0.y; num[2] += ev * v0.z; num[3] += ev * v0.w;
            num[4] += ev * v1.x; num[5] += ev * v1.y; num[6] += ev * v1.z; num[7] += ev * v1.w;
        }
        float inv = (den > 0.f) ? 1.0f / den : 0.0f;
        #pragma unroll
        for (int i = 0; i < 8; i++) out[i] += num[i] * inv;
    }

    float* ap = g_acc_op + (size_t)w * 256 + lane * 8;
    *(float4*)(ap)     = make_float4(out[0], out[1], out[2], out[3]);
    *(float4*)(ap + 4) = make_float4(out[4], out[5], out[6], out[7]);
}

__device__ void gather_m_body(int n, const float* __restrict__ prel)
{
    __shared__ float snum[8][256];
    __shared__ float sden[8][8];
    int warp = threadIdx.x >> 5, lane = threadIdx.x & 31;
    int h = lane >> 2;
    int beg = g_off4[2][n], end = g_off4[2][n + 1];

    const float4* qp = (const float4*)(g_q_m + (size_t)n * 256);
    float4 q0 = qp[lane * 2], q1 = qp[lane * 2 + 1];
    float ps = prel[2 * HH + h] * 0.17677669529663687f;

    float num[8] = {0.f, 0.f, 0.f, 0.f, 0.f, 0.f, 0.f, 0.f};
    float den = 0.0f;

    for (int j = beg + warp; j < end; j += 8) {
        int src = g_esrc4[2][j];
        const float4* kp = (const float4*)(g_KT[2] + (size_t)src * 256);
        const float4* vp = (const float4*)(g_VT[2] + (size_t)src * 256);
        float4 k0 = kp[lane * 2], k1 = kp[lane * 2 + 1];
        float4 v0 = vp[lane * 2], v1 = vp[lane * 2 + 1];
        float s = q0.x * k0.x + q0.y * k0.y + q0.z * k0.z + q0.w * k0.w
                + q1.x * k1.x + q1.y * k1.y + q1.z * k1.z + q1.w * k1.w;
        s += __shfl_xor_sync(0xffffffffu, s, 1);
        s += __shfl_xor_sync(0xffffffffu, s, 2);
        float ev = expf(s * ps);
        den += ev;
        num[0] += ev * v0.x; num[1] += ev * v0.y; num[2] += ev * v0.z; num[3] += ev * v0.w;
        num[4] += ev * v1.x; num[5] += ev * v1.y; num[6] += ev * v1.z; num[7] += ev * v1.w;
    }
    #pragma unroll
    for (int i = 0; i < 8; i += 4)
        *(float4*)&snum[warp][lane * 8 + i] = make_float4(num[i], num[i+1], num[i+2], num[i+3]);
    if ((lane & 3) == 0) sden[warp][h] = den;
    __syncthreads();

    {
        int c = threadIdx.x;
        float tot = 0.0f;
        #pragma unroll
        for (int ww = 0; ww < 8; ww++) tot += snum[ww][c];
        int hh = c >> 5;
        float d = 0.0f;
        #pragma unroll
        for (int ww = 0; ww < 8; ww++) d += sden[ww][hh];
        g_acc_m[(size_t)n * 256 + c] = (d > 0.f) ? tot / d : 0.0f;
    }
}

// ---------------- launch 4: both gathers ----------------
__global__ void __launch_bounds__(256) fused_gather(const float* __restrict__ prel)
{
    int b = blockIdx.x;
    if (b < GOP_BLOCKS) gather_op_body(b, prel);
    else                gather_m_body(b - GOP_BLOCKS, prel);
}

// ---------------- launch 5: both final FUSE GEMMs ----------------
__global__ void __launch_bounds__(256, 2) gemm_final(
    const float* __restrict__ accop, const float* __restrict__ accm,
    const float* __restrict__ Wa, const float* __restrict__ ba,
    const float* __restrict__ xop, const float* __restrict__ xm,
    const float* __restrict__ skipv, float* __restrict__ out)
{
    extern __shared__ uint32_t dynsmem[];
    int t = blockIdx.x;
    bool isM = t >= TILES_OP;
    int tt = isM ? t - TILES_OP : t;
    int rowBase = (tt >> 1) * 128;
    int colBase = (tt & 1) * 128;

    const float* A = isM ? accm : accop;
    int N = isM ? NMM : NOP;
    const float* W = Wa + (isM ? DD * DD : 0);
    const float* b = ba + (isM ? DD : 0);
    const float* xs = isM ? xm : xop;
    float* C = out + (isM ? (size_t)NOP * DD : 0);
    float sa = 1.0f / (1.0f + expf(-skipv[isM ? 1 : 0]));

    gemm_tile_tc<true>(dynsmem, A, W, b, C, N, xs, sa, rowBase, colBase);
}

// ---------------- host side ----------------
static float* symaddr(const void* sym) {
    void* p = nullptr;
    cudaGetSymbolAddress(&p, sym);
    return (float*)p;
}

extern "C" void kernel_launch(void* const* d_in, const int* in_sizes, int n_in,
                              void* d_out, int out_size)
{
    const float* x_op    = (const float*)d_in[0];
    const float* x_m     = (const float*)d_in[1];
    const float* delta_t = (const float*)d_in[2];
    const int*   ei0 = (const int*)d_in[3];
    const int*   ei1 = (const int*)d_in[4];
    const int*   ei2 = (const int*)d_in[5];
    const int*   ei3 = (const int*)d_in[6];
    const float* Wt   = (const float*)d_in[7];
    const float* bt   = (const float*)d_in[8];
    const float* ln_g = (const float*)d_in[9];
    const float* ln_b = (const float*)d_in[10];
    const float* Wk   = (const float*)d_in[11];
    const float* bk   = (const float*)d_in[12];
    const float* Wq   = (const float*)d_in[13];
    const float* bq   = (const float*)d_in[14];
    const float* Wv   = (const float*)d_in[15];
    const float* bv   = (const float*)d_in[16];
    const float* Wa   = (const float*)d_in[17];
    const float* ba   = (const float*)d_in[18];
    const float* skip = (const float*)d_in[19];
    const float* a_rel = (const float*)d_in[20];
    const float* m_rel = (const float*)d_in[21];
    const float* p_rel = (const float*)d_in[22];
    float* out = (float*)d_out;

    float* xw    = symaddr(g_xw);
    float* k_op  = symaddr(g_k_op);
    float* q_op  = symaddr(g_q_op);
    float* v_op  = symaddr(g_v_op);
    float* k_m   = symaddr(g_k_m);
    float* q_m   = symaddr(g_q_m);
    float* v_m   = symaddr(g_v_m);
    float* acc_op = symaddr(g_acc_op);
    float* acc_m  = symaddr(g_acc_m);
    int*   cur4  = (int*)symaddr(g_cur4);

    static bool attr_done = false;
    if (!attr_done) {
        cudaFuncSetAttribute(fused_kqv_scan,
                             cudaFuncAttributeMaxDynamicSharedMemorySize, DYN_BYTES);
        cudaFuncSetAttribute(gemm_final,
                             cudaFuncAttributeMaxDynamicSharedMemorySize, DYN_BYTES);
        attr_done = true;
    }

    cudaMemcpyAsync(xw, x_op, (size_t)NOP * DD * sizeof(float), cudaMemcpyDeviceToDevice);
    cudaMemsetAsync(cur4, 0, (size_t)4 * NOP * sizeof(int));

    // L1: temporal encoding + CSR degree count
    fused_temporal_count<<<TEMP_BLOCKS + 4 * CNT_BPT, 256>>>(
        delta_t, ei0, ei1, ei2, ei3, Wt, bt, ln_g, ln_b);

    // L2: 6 k/q/v GEMMs (double-buffered 3xTF32) + 4 CSR scans
    fused_kqv_scan<<<3 * TILES_ALL + 4, 256, DYN_BYTES>>>(
        xw, x_m, Wk, Wq, Wv, bk, bq, bv,
        k_op, q_op, v_op, k_m, q_m, v_m);

    // L3: relation transforms (tensor core) + CSR fill
    fused_rel_fill<<<REL_TC + 4 * CNT_BPT, 256>>>(a_rel, m_rel, ei0, ei1, ei2, ei3);

    // L4: both gathers
    fused_gather<<<GOP_BLOCKS + NMM, 256>>>(p_rel);

    // L5: both final GEMMs (double-buffered tensor core)
    gemm_final<<<TILES_ALL, 256, DYN_BYTES>>>(acc_op, acc_m, Wa, ba, xw, x_m, skip, out);
}

// round 16
// speedup vs baseline: 1.0461x; 1.0056x over previous
#include <cuda_runtime.h>
#include <math.h>
#include <stdint.h>

#define NOP 20000
#define NMM 500
#define DD  256
#define HH  8
#define DHD 32
#define TDE 16
#define EE  200000

#define TILES_OP 314   // 157 rowblocks x 2 colblocks
#define TILES_M  8     // 4 x 2
#define TILES_ALL (TILES_OP + TILES_M)

#define TEMP_BLOCKS 782            // ceil(EE/256), 256 edges per block
#define CNT_BPT 782                // count blocks per edge type: ceil(EE/256)
#define RELB_PER_H 313             // ceil(NOP/64) node-blocks per (type<3, head)
#define RELB_OP (RELB_PER_H * HH)  // 2504 per op-src type
#define RELB_M_PER_H 8             // ceil(NMM/64)
#define REL_TC (3 * RELB_OP + RELB_M_PER_H * HH)   // 7576
#define GOP_BLOCKS 2500            // NOP*32/256

#define SMP 20
#define PIECE (128 * SMP)          // 2560 u32 per matrix piece
#define BUFU32 (4 * PIECE)         // Ah|Al|Bh|Bl = 10240 u32 per buffer
#define DYN_BYTES (2 * BUFU32 * 4) // 81920 bytes

// ---------------- scratch ----------------
__device__ float g_xw[NOP * DD];
__device__ float g_k_op[NOP * DD];
__device__ float g_q_op[NOP * DD];
__device__ float g_v_op[NOP * DD];
__device__ float g_k_m[NMM * DD];
__device__ float g_q_m[NMM * DD];
__device__ float g_v_m[NMM * DD];
__device__ float g_KT[3][NOP * DD];
__device__ float g_VT[3][NOP * DD];
__device__ float g_KTm[NMM * DD];
__device__ float g_VTm[NMM * DD];
__device__ float g_acc_op[NOP * DD];
__device__ float g_acc_m[NMM * DD];
__device__ int   g_off4[4][NOP + 1];
__device__ int   g_cur4[4][NOP];
__device__ int   g_esrc4[4][EE];

__device__ __forceinline__ float gelu_exact(float x) {
    return 0.5f * x * (1.0f + erff(x * 0.70710678118654752f));
}

__device__ __forceinline__ void red_add_v4(float* p, float a, float b, float c, float d) {
    asm volatile("red.global.add.v4.f32 [%0], {%1, %2, %3, %4};"
                 :: "l"(p), "f"(a), "f"(b), "f"(c), "f"(d) : "memory");
}

__device__ __forceinline__ uint32_t cvt_tf32(float x) {
    uint32_t r; asm("cvt.rna.tf32.f32 %0, %1;" : "=r"(r) : "f"(x)); return r;
}

__device__ __forceinline__ void mma_tf32(float* c, const uint32_t* a, const uint32_t* b) {
    asm volatile("mma.sync.aligned.m16n8k8.row.col.f32.tf32.tf32.f32 "
                 "{%0,%1,%2,%3}, {%4,%5,%6,%7}, {%8,%9}, {%0,%1,%2,%3};"
                 : "+f"(c[0]), "+f"(c[1]), "+f"(c[2]), "+f"(c[3])
                 : "r"(a[0]), "r"(a[1]), "r"(a[2]), "r"(a[3]),
                   "r"(b[0]), "r"(b[1]));
}

// ---------------- temporal encoding: 256 edges per block, 8 warps x 32 edges ----------------
__device__ void temporal_body(int blk,
                              const float* __restrict__ delta_t,
                              const int* __restrict__ ei_src,
                              const float* __restrict__ Wt,
                              const float* __restrict__ bt,
                              const float* __restrict__ ln_g,
                              const float* __restrict__ ln_b)
{
    __shared__ float Wts[TDE * DD];
    __shared__ float bts[DD], gs[DD], bs[DD];
    __shared__ float tr[8][DD];
    for (int idx = threadIdx.x; idx < DD * TDE; idx += blockDim.x) {
        int j = idx / TDE, i = idx % TDE;
        Wts[i * DD + j] = Wt[idx];
    }
    for (int idx = threadIdx.x; idx < DD; idx += blockDim.x) {
        bts[idx] = bt[idx]; gs[idx] = ln_g[idx]; bs[idx] = ln_b[idx];
    }
    __syncthreads();

    int warp = threadIdx.x >> 5;
    int lane = threadIdx.x & 31;

    float freqs[8];
    #pragma unroll
    for (int m = 0; m < 8; m++)
        freqs[m] = exp2f(-(float)m * (9.965784284662087f / 8.0f));  // 1000^{-m/8}

    #pragma unroll 1
    for (int t = 0; t < 32; t++) {
        int w = blk * 256 + warp * 32 + t;
        if (w >= EE) break;

        float dt = delta_t[w];
        int src = ei_src[w];

        float sn[8], cn[8];
        #pragma unroll
        for (int m = 0; m < 8; m++) sincosf(dt * freqs[m], &sn[m], &cn[m]);

        float pt[8];
        float lsum = 0.0f;
        #pragma unroll
        for (int jj = 0; jj < 8; jj++) {
            int j = lane + jj * 32;
            float s = bts[j];
            #pragma unroll
            for (int m = 0; m < 8; m++)
                s += sn[m] * Wts[(2 * m) * DD + j] + cn[m] * Wts[(2 * m + 1) * DD + j];
            pt[jj] = s;
            lsum += s;
        }
        #pragma unroll
        for (int o = 16; o; o >>= 1) lsum += __shfl_xor_sync(0xffffffffu, lsum, o);
        float mu = lsum * (1.0f / 256.0f);

        float lvar = 0.0f;
        #pragma unroll
        for (int jj = 0; jj < 8; jj++) { float d = pt[jj] - mu; lvar += d * d; }
        #pragma unroll
        for (int o = 16; o; o >>= 1) lvar += __shfl_xor_sync(0xffffffffu, lvar, o);
        float rstd = rsqrtf(lvar * (1.0f / 256.0f) + 1e-5f);

        #pragma unroll
        for (int jj = 0; jj < 8; jj++) {
            int j = lane + jj * 32;
            tr[warp][j] = (pt[jj] - mu) * rstd * gs[j] + bs[j];
        }
        __syncwarp();
        float4 y0 = *(const float4*)&tr[warp][lane * 8];
        float4 y1 = *(const float4*)&tr[warp][lane * 8 + 4];
        float* xp = &g_xw[(size_t)src * DD + lane * 8];
        red_add_v4(xp,     y0.x, y0.y, y0.z, y0.w);
        red_add_v4(xp + 4, y1.x, y1.y, y1.z, y1.w);
        __syncwarp();
    }
}

// ---------------- launch 1: temporal + CSR count ----------------
__global__ void __launch_bounds__(256) fused_temporal_count(
    const float* __restrict__ delta_t,
    const int* __restrict__ e0, const int* __restrict__ e1,
    const int* __restrict__ e2, const int* __restrict__ e3,
    const float* __restrict__ Wt, const float* __restrict__ bt,
    const float* __restrict__ ln_g, const float* __restrict__ ln_b)
{
    int b = blockIdx.x;
    if (b < TEMP_BLOCKS) {
        temporal_body(b, delta_t, e0, Wt, bt, ln_g, ln_b);
    } else {
        int cb = b - TEMP_BLOCKS;
        int ty = cb / CNT_BPT;
        int i = (cb % CNT_BPT) * 256 + threadIdx.x;
        if (i < EE) {
            const int* ei = (ty == 0) ? e0 : (ty == 1) ? e1 : (ty == 2) ? e2 : e3;
            atomicAdd(&g_cur4[ty][ei[EE + i]], 1);
        }
    }
}

// ---------------- tensor-core 3xTF32 GEMM tile: 128x128, K=256, double-buffered (1 sync/iter) ----------------
__device__ __forceinline__ void split_store(uint32_t* H, uint32_t* L, int idx, float4 v) {
    uint32_t h0 = cvt_tf32(v.x), h1 = cvt_tf32(v.y), h2 = cvt_tf32(v.z), h3 = cvt_tf32(v.w);
    uint32_t l0 = cvt_tf32(v.x - __uint_as_float(h0));
    uint32_t l1 = cvt_tf32(v.y - __uint_as_float(h1));
    uint32_t l2 = cvt_tf32(v.z - __uint_as_float(h2));
    uint32_t l3 = cvt_tf32(v.w - __uint_as_float(h3));
    *(uint4*)&H[idx] = make_uint4(h0, h1, h2, h3);
    *(uint4*)&L[idx] = make_uint4(l0, l1, l2, l3);
}

template <bool FUSE>
__device__ __forceinline__ void gemm_tile_tc(
    uint32_t* smem,
    const float* __restrict__ A, const float* __restrict__ W,
    const float* __restrict__ bias, float* __restrict__ C, int N,
    const float* __restrict__ xsrc, float sa, int rowBase, int colBase)
{
    int tid = threadIdx.x;
    int lane = tid & 31;
    int wid = tid >> 5;
    int mwarp = wid >> 2;
    int nwarp = wid & 3;
    int grp  = lane >> 2;
    int tid4 = lane & 3;

    int row0 = tid >> 2, q0 = (tid & 3) * 4;
    int row1 = row0 + 64;
    int gr0 = rowBase + row0, gr1 = rowBase + row1;
    int gc0 = colBase + row0, gc1 = colBase + row1;

    float acc[4][4][4];
    #pragma unroll
    for (int i = 0; i < 4; i++)
        #pragma unroll
        for (int j = 0; j < 4; j++)
            #pragma unroll
            for (int r = 0; r < 4; r++) acc[i][j][r] = 0.0f;

    float4 av0, av1, bv0, bv1;
    auto ldg = [&](int kt) {
        av0 = make_float4(0.f, 0.f, 0.f, 0.f);
        av1 = make_float4(0.f, 0.f, 0.f, 0.f);
        if (gr0 < N) av0 = *(const float4*)(A + (size_t)gr0 * 256 + kt + q0);
        if (gr1 < N) av1 = *(const float4*)(A + (size_t)gr1 * 256 + kt + q0);
        if (FUSE) {
            av0.x = gelu_exact(av0.x); av0.y = gelu_exact(av0.y);
            av0.z = gelu_exact(av0.z); av0.w = gelu_exact(av0.w);
            av1.x = gelu_exact(av1.x); av1.y = gelu_exact(av1.y);
            av1.z = gelu_exact(av1.z); av1.w = gelu_exact(av1.w);
        }
        bv0 = *(const float4*)(W + (size_t)gc0 * 256 + kt + q0);
        bv1 = *(const float4*)(W + (size_t)gc1 * 256 + kt + q0);
    };
    auto sts = [&](int buf) {
        uint32_t* Ah = smem + buf * BUFU32;
        uint32_t* Al = Ah + PIECE;
        uint32_t* Bh = Ah + 2 * PIECE;
        uint32_t* Bl = Ah + 3 * PIECE;
        split_store(Ah, Al, row0 * SMP + q0, av0);
        split_store(Ah, Al, row1 * SMP + q0, av1);
        split_store(Bh, Bl, row0 * SMP + q0, bv0);
        split_store(Bh, Bl, row1 * SMP + q0, bv1);
    };

    ldg(0);
    sts(0);

    for (int it = 0; it < 16; it++) {
        __syncthreads();
        if (it < 15) ldg((it + 1) * 16);

        const uint32_t* Ah = smem + (it & 1) * BUFU32;
        const uint32_t* Al = Ah + PIECE;
        const uint32_t* Bh = Ah + 2 * PIECE;
        const uint32_t* Bl = Ah + 3 * PIECE;

        #pragma unroll
        for (int s = 0; s < 2; s++) {
            int kb = s * 8 + tid4;
            uint32_t ah[4][4], al[4][4];
            #pragma unroll
            for (int mt = 0; mt < 4; mt++) {
                int base = (mwarp * 64 + mt * 16 + grp) * SMP + kb;
                ah[mt][0] = Ah[base];            al[mt][0] = Al[base];
                ah[mt][1] = Ah[base + 8 * SMP];  al[mt][1] = Al[base + 8 * SMP];
                ah[mt][2] = Ah[base + 4];        al[mt][2] = Al[base + 4];
                ah[mt][3] = Ah[base + 8 * SMP + 4]; al[mt][3] = Al[base + 8 * SMP + 4];
            }
            uint32_t bh[4][2], bl[4][2];
            #pragma unroll
            for (int nt = 0; nt < 4; nt++) {
                int base = (nwarp * 32 + nt * 8 + grp) * SMP + kb;
                bh[nt][0] = Bh[base];     bl[nt][0] = Bl[base];
                bh[nt][1] = Bh[base + 4]; bl[nt][1] = Bl[base + 4];
            }
            #pragma unroll
            for (int mt = 0; mt < 4; mt++)
                #pragma unroll
                for (int nt = 0; nt < 4; nt++) {
                    mma_tf32(acc[mt][nt], ah[mt], bh[nt]);
                    mma_tf32(acc[mt][nt], ah[mt], bl[nt]);
                    mma_tf32(acc[mt][nt], al[mt], bh[nt]);
                }
        }
        if (it < 15) sts((it + 1) & 1);   // writes the buffer NOT being read this iter
    }

    #pragma unroll
    for (int mt = 0; mt < 4; mt++) {
        int r0g = rowBase + mwarp * 64 + mt * 16 + grp;
        int r1g = r0g + 8;
        #pragma unroll
        for (int nt = 0; nt < 4; nt++) {
            int c = colBase + nwarp * 32 + nt * 8 + tid4 * 2;
            float2 bi = *(const float2*)(bias + c);
            if (r0g < N) {
                float o0 = acc[mt][nt][0] + bi.x;
                float o1 = acc[mt][nt][1] + bi.y;
                if (FUSE) {
                    float2 xs = *(const float2*)(xsrc + (size_t)r0g * 256 + c);
                    o0 = sa * o0 + (1.0f - sa) * xs.x;
                    o1 = sa * o1 + (1.0f - sa) * xs.y;
                }
                *(float2*)(C + (size_t)r0g * 256 + c) = make_float2(o0, o1);
            }
            if (r1g < N) {
                float o2 = acc[mt][nt][2] + bi.x;
                float o3 = acc[mt][nt][3] + bi.y;
                if (FUSE) {
                    float2 xs = *(const float2*)(xsrc + (size_t)r1g * 256 + c);
                    o2 = sa * o2 + (1.0f - sa) * xs.x;
                    o3 = sa * o3 + (1.0f - sa) * xs.y;
                }
                *(float2*)(C + (size_t)r1g * 256 + c) = make_float2(o2, o3);
            }
        }
    }
}

// 256-thread exclusive scan of g_cur4[ty] -> g_off4[ty]; cur := offset
__device__ void csr_scan_body(int ty) {
    int Nd = (ty == 2) ? NMM : NOP;
    __shared__ int sp[256];
    int tid = threadIdx.x;
    int chunk = (Nd + 255) / 256;
    int beg = tid * chunk;
    int end = beg + chunk; if (end > Nd) end = Nd;
    int s = 0;
    for (int i = beg; i < end; i++) s += g_cur4[ty][i];
    sp[tid] = s;
    __syncthreads();
    #pragma unroll
    for (int o = 1; o < 256; o <<= 1) {
        int v = (tid >= o) ? sp[tid - o] : 0;
        __syncthreads();
        sp[tid] += v;
        __syncthreads();
    }
    int base = (tid == 0) ? 0 : sp[tid - 1];
    for (int i = beg; i < end; i++) {
        int d = g_cur4[ty][i];
        g_off4[ty][i] = base;
        g_cur4[ty][i] = base;
        base += d;
    }
    if (tid == 255) g_off4[ty][Nd] = sp[255];
}

// ---------------- launch 2: 6 k/q/v GEMMs + 4 CSR scans ----------------
__global__ void __launch_bounds__(256, 2) fused_kqv_scan(
    const float* __restrict__ Aop, const float* __restrict__ Am,
    const float* __restrict__ Wk, const float* __restrict__ Wq, const float* __restrict__ Wv,
    const float* __restrict__ bk, const float* __restrict__ bq, const float* __restrict__ bv,
    float* __restrict__ kop, float* __restrict__ qop, float* __restrict__ vop,
    float* __restrict__ km,  float* __restrict__ qm,  float* __restrict__ vm)
{
    extern __shared__ uint32_t dynsmem[];
    int b = blockIdx.x;
    if (b < 3 * TILES_ALL) {
        int z = b / TILES_ALL;
        int t = b % TILES_ALL;
        bool isM = t >= TILES_OP;
        int tt = isM ? t - TILES_OP : t;
        int rowBase = (tt >> 1) * 128;
        int colBase = (tt & 1) * 128;

        const float* A = isM ? Am : Aop;
        int N = isM ? NMM : NOP;
        const float* W = (z == 0 ? Wk : z == 1 ? Wq : Wv) + (isM ? DD * DD : 0);
        const float* bb = (z == 0 ? bk : z == 1 ? bq : bv) + (isM ? DD : 0);
        float* C = isM ? (z == 0 ? km : z == 1 ? qm : vm)
                       : (z == 0 ? kop : z == 1 ? qop : vop);
        gemm_tile_tc<false>(dynsmem, A, W, bb, C, N, nullptr, 0.0f, rowBase, colBase);
    } else {
        csr_scan_body(b - 3 * TILES_ALL);
    }
}

// ---------------- tensor-core rel transform: [64 x 32] @ [32 x 32] per (e,h) block ----------------
__device__ void rel_body_tc(int e, int h, int xb,
                            const float* __restrict__ arel,
                            const float* __restrict__ mrel)
{
    int N = (e == 3) ? NMM : NOP;
    int nBase = xb * 64;
    if (nBase >= N) return;

    const float* ktab = (e == 3) ? g_k_m : g_k_op;
    const float* vtab = (e == 3) ? g_v_m : g_v_op;
    float* KT = (e == 3) ? g_KTm : g_KT[e];
    float* VT = (e == 3) ? g_VTm : g_VT[e];

    __shared__ uint32_t Ah[64 * 36], Al[64 * 36];
    __shared__ uint32_t Bah[32 * 36], Bal[32 * 36], Bmh[32 * 36], Bml[32 * 36];

    int tid = threadIdx.x, lane = tid & 31, wid = tid >> 5;
    int grp = lane >> 2, tid4 = lane & 3;
    int mt = wid & 3;
    int ntbase = (wid >> 2) * 2;

    for (int i = tid; i < 1024; i += 256) {
        int d = i >> 5, f = i & 31;
        float va = arel[((size_t)(e * HH + h)) * 1024 + i];
        float vm = mrel[((size_t)(e * HH + h)) * 1024 + i];
        uint32_t hh = cvt_tf32(va);
        Bah[f * 36 + d] = hh;
        Bal[f * 36 + d] = cvt_tf32(va - __uint_as_float(hh));
        hh = cvt_tf32(vm);
        Bmh[f * 36 + d] = hh;
        Bml[f * 36 + d] = cvt_tf32(vm - __uint_as_float(hh));
    }

    #pragma unroll
    for (int phase = 0; phase < 2; phase++) {
        const float* xt = phase ? vtab : ktab;
        __syncthreads();
        for (int q = tid; q < 512; q += 256) {
            int r = q >> 3, c4 = (q & 7) * 4;
            float4 v = make_float4(0.f, 0.f, 0.f, 0.f);
            if (nBase + r < N)
                v = *(const float4*)(xt + (size_t)(nBase + r) * 256 + h * 32 + c4);
            uint32_t h0 = cvt_tf32(v.x), h1 = cvt_tf32(v.y), h2 = cvt_tf32(v.z), h3 = cvt_tf32(v.w);
            int idx = r * 36 + c4;
            Ah[idx] = h0; Ah[idx + 1] = h1; Ah[idx + 2] = h2; Ah[idx + 3] = h3;
            Al[idx]     = cvt_tf32(v.x - __uint_as_float(h0));
            Al[idx + 1] = cvt_tf32(v.y - __uint_as_float(h1));
            Al[idx + 2] = cvt_tf32(v.z - __uint_as_float(h2));
            Al[idx + 3] = cvt_tf32(v.w - __uint_as_float(h3));
        }
        __syncthreads();

        const uint32_t* Bh = phase ? Bmh : Bah;
        const uint32_t* Bl = phase ? Bml : Bal;
        float acc[2][4];
        #pragma unroll
        for (int j = 0; j < 2; j++)
            #pragma unroll
            for (int r = 0; r < 4; r++) acc[j][r] = 0.0f;

        #pragma unroll
        for (int kc = 0; kc < 4; kc++) {
            int kb = kc * 8 + tid4;
            int ab = (mt * 16 + grp) * 36 + kb;
            uint32_t ah[4] = {Ah[ab], Ah[ab + 8 * 36], Ah[ab + 4], Ah[ab + 8 * 36 + 4]};
            uint32_t al[4] = {Al[ab], Al[ab + 8 * 36], Al[ab + 4], Al[ab + 8 * 36 + 4]};
            #pragma unroll
            for (int j = 0; j < 2; j++) {
                int bb = ((ntbase + j) * 8 + grp) * 36 + kb;
                uint32_t bh[2] = {Bh[bb], Bh[bb + 4]};
                uint32_t bl[2] = {Bl[bb], Bl[bb + 4]};
                mma_tf32(acc[j], ah, bh);
                mma_tf32(acc[j], ah, bl);
                mma_tf32(acc[j], al, bh);
            }
        }

        float* OUT = phase ? VT : KT;
        int r0 = nBase + mt * 16 + grp;
        int r1 = r0 + 8;
        #pragma unroll
        for (int j = 0; j < 2; j++) {
            int c = (ntbase + j) * 8 + tid4 * 2;
            if (r0 < N)
                *(float2*)(OUT + (size_t)r0 * 256 + h * 32 + c) = make_float2(acc[j][0], acc[j][1]);
            if (r1 < N)
                *(float2*)(OUT + (size_t)r1 * 256 + h * 32 + c) = make_float2(acc[j][2], acc[j][3]);
        }
    }
}

// ---------------- launch 3: rel transforms (TC) + CSR fill ----------------
__global__ void __launch_bounds__(256) fused_rel_fill(
    const float* __restrict__ arel, const float* __restrict__ mrel,
    const int* __restrict__ e0, const int* __restrict__ e1,
    const int* __restrict__ e2, const int* __restrict__ e3)
{
    int b = blockIdx.x;
    if (b < 3 * RELB_OP) {
        int e = b / RELB_OP;
        int rem = b % RELB_OP;
        int h = rem / RELB_PER_H;
        int xb = rem % RELB_PER_H;
        rel_body_tc(e, h, xb, arel, mrel);
    } else if (b < REL_TC) {
        int b2 = b - 3 * RELB_OP;
        int h = b2 / RELB_M_PER_H;
        int xb = b2 % RELB_M_PER_H;
        rel_body_tc(3, h, xb, arel, mrel);
    } else {
        int cb = b - REL_TC;
        int ty = cb / CNT_BPT;
        int i = (cb % CNT_BPT) * 256 + threadIdx.x;
        if (i < EE) {
            const int* ei = (ty == 0) ? e0 : (ty == 1) ? e1 : (ty == 2) ? e2 : e3;
            int dst = ei[EE + i];
            int src = ei[i];
            int pos = atomicAdd(&g_cur4[ty][dst], 1);
            g_esrc4[ty][pos] = src;
        }
    }
}

// ---------------- gather bodies ----------------
__device__ void gather_op_body(int b, const float* __restrict__ prel)
{
    int w = b * 8 + (threadIdx.x >> 5);
    int lane = threadIdx.x & 31;
    if (w >= NOP) return;

    const float4* qp = (const float4*)(g_q_op + (size_t)w * 256);
    float4 q0 = qp[lane * 2], q1 = qp[lane * 2 + 1];
    int h = lane >> 2;

    float out[8] = {0.f, 0.f, 0.f, 0.f, 0.f, 0.f, 0.f, 0.f};

    #pragma unroll
    for (int pass = 0; pass < 3; pass++) {
        int e = (pass == 2) ? 3 : pass;
        const float* KT = (pass == 2) ? g_KTm : g_KT[e];
        const float* VT = (pass == 2) ? g_VTm : g_VT[e];
        float ps = prel[e * HH + h] * 0.17677669529663687f;   // 1/sqrt(32)

        int beg = g_off4[e][w], end = g_off4[e][w + 1];
        float num[8] = {0.f, 0.f, 0.f, 0.f, 0.f, 0.f, 0.f, 0.f};
        float den = 0.0f;
        #pragma unroll 2
        for (int j = beg; j < end; j++) {
            int src = g_esrc4[e][j];
            const float4* kp = (const float4*)(KT + (size_t)src * 256);
            const float4* vp = (const float4*)(VT + (size_t)src * 256);
            float4 k0 = kp[lane * 2], k1 = kp[lane * 2 + 1];
            float4 v0 = vp[lane * 2], v1 = vp[lane * 2 + 1];
            float s = q0.x * k0.x + q0.y * k0.y + q0.z * k0.z + q0.w * k0.w
                    + q1.x * k1.x + q1.y * k1.y + q1.z * k1.z + q1.w * k1.w;
            s += __shfl_xor_sync(0xffffffffu, s, 1);
            s += __shfl_xor_sync(0xffffffffu, s, 2);
            float ev = expf(s * ps);
            den += ev;
            num[0] += ev * v0.x; num[1] += ev * v0.y; num[2] += ev * v0.z; num[3] += ev * v0.w;
            num[4] += ev * v1.x; num[5] += ev * v1.y; num[6] += ev * v1.z; num[7] += ev * v1.w;
        }
        float inv = (den > 0.f) ? 1.0f / den : 0.0f;
        #pragma unroll
        for (int i = 0; i < 8; i++) out[i] += num[i] * inv;
    }

    float* ap = g_acc_op + (size_t)w * 256 + lane * 8;
    *(float4*)(ap)     = make_float4(out[0], out[1], out[2], out[3]);
    *(float4*)(ap + 4) = make_float4(out[4], out[5], out[6], out[7]);
}

__device__ void gather_m_body(int n, const float* __restrict__ prel)
{
    __shared__ float snum[8][256];
    __shared__ float sden[8][8];
    int warp = threadIdx.x >> 5, lane = threadIdx.x & 31;
    int h = lane >> 2;
    int beg = g_off4[2][n], end = g_off4[2][n + 1];

    const float4* qp = (const float4*)(g_q_m + (size_t)n * 256);
    float4 q0 = qp[lane * 2], q1 = qp[lane * 2 + 1];
    float ps = prel[2 * HH + h] * 0.17677669529663687f;

    float num[8] = {0.f, 0.f, 0.f, 0.f, 0.f, 0.f, 0.f, 0.f};
    float den = 0.0f;

    for (int j = beg + warp; j < end; j += 8) {
        int src = g_esrc4[2][j];
        const float4* kp = (const float4*)(g_KT[2] + (size_t)src * 256);
        const float4* vp = (const float4*)(g_VT[2] + (size_t)src * 256);
        float4 k0 = kp[lane * 2], k1 = kp[lane * 2 + 1];
        float4 v0 = vp[lane * 2], v1 = vp[lane * 2 + 1];
        float s = q0.x * k0.x + q0.y * k0.y + q0.z * k0.z + q0.w * k0.w
                + q1.x * k1.x + q1.y * k1.y + q1.z * k1.z + q1.w * k1.w;
        s += __shfl_xor_sync(0xffffffffu, s, 1);
        s += __shfl_xor_sync(0xffffffffu, s, 2);
        float ev = expf(s * ps);
        den += ev;
        num[0] += ev * v0.x; num[1] += ev * v0.y; num[2] += ev * v0.z; num[3] += ev * v0.w;
        num[4] += ev * v1.x; num[5] += ev * v1.y; num[6] += ev * v1.z; num[7] += ev * v1.w;
    }
    #pragma unroll
    for (int i = 0; i < 8; i += 4)
        *(float4*)&snum[warp][lane * 8 + i] = make_float4(num[i], num[i+1], num[i+2], num[i+3]);
    if ((lane & 3) == 0) sden[warp][h] = den;
    __syncthreads();

    {
        int c = threadIdx.x;
        float tot = 0.0f;
        #pragma unroll
        for (int ww = 0; ww < 8; ww++) tot += snum[ww][c];
        int hh = c >> 5;
        float d = 0.0f;
        #pragma unroll
        for (int ww = 0; ww < 8; ww++) d += sden[ww][hh];
        g_acc_m[(size_t)n * 256 + c] = (d > 0.f) ? tot / d : 0.0f;
    }
}

// ---------------- launch 4: both gathers ----------------
__global__ void __launch_bounds__(256) fused_gather(const float* __restrict__ prel)
{
    int b = blockIdx.x;
    if (b < GOP_BLOCKS) gather_op_body(b, prel);
    else                gather_m_body(b - GOP_BLOCKS, prel);
}

// ---------------- launch 5: both final FUSE GEMMs ----------------
__global__ void __launch_bounds__(256, 2) gemm_final(
    const float* __restrict__ accop, const float* __restrict__ accm,
    const float* __restrict__ Wa, const float* __restrict__ ba,
    const float* __restrict__ xop, const float* __restrict__ xm,
    const float* __restrict__ skipv, float* __restrict__ out)
{
    extern __shared__ uint32_t dynsmem[];
    int t = blockIdx.x;
    bool isM = t >= TILES_OP;
    int tt = isM ? t - TILES_OP : t;
    int rowBase = (tt >> 1) * 128;
    int colBase = (tt & 1) * 128;

    const float* A = isM ? accm : accop;
    int N = isM ? NMM : NOP;
    const float* W = Wa + (isM ? DD * DD : 0);
    const float* b = ba + (isM ? DD : 0);
    const float* xs = isM ? xm : xop;
    float* C = out + (isM ? (size_t)NOP * DD : 0);
    float sa = 1.0f / (1.0f + expf(-skipv[isM ? 1 : 0]));

    gemm_tile_tc<true>(dynsmem, A, W, b, C, N, xs, sa, rowBase, colBase);
}

// ---------------- host side ----------------
static float* symaddr(const void* sym) {
    void* p = nullptr;
    cudaGetSymbolAddress(&p, sym);
    return (float*)p;
}

extern "C" void kernel_launch(void* const* d_in, const int* in_sizes, int n_in,
                              void* d_out, int out_size)
{
    const float* x_op    = (const float*)d_in[0];
    const float* x_m     = (const float*)d_in[1];
    const float* delta_t = (const float*)d_in[2];
    const int*   ei0 = (const int*)d_in[3];
    const int*   ei1 = (const int*)d_in[4];
    const int*   ei2 = (const int*)d_in[5];
    const int*   ei3 = (const int*)d_in[6];
    const float* Wt   = (const float*)d_in[7];
    const float* bt   = (const float*)d_in[8];
    const float* ln_g = (const float*)d_in[9];
    const float* ln_b = (const float*)d_in[10];
    const float* Wk   = (const float*)d_in[11];
    const float* bk   = (const float*)d_in[12];
    const float* Wq   = (const float*)d_in[13];
    const float* bq   = (const float*)d_in[14];
    const float* Wv   = (const float*)d_in[15];
    const float* bv   = (const float*)d_in[16];
    const float* Wa   = (const float*)d_in[17];
    const float* ba   = (const float*)d_in[18];
    const float* skip = (const float*)d_in[19];
    const float* a_rel = (const float*)d_in[20];
    const float* m_rel = (const float*)d_in[21];
    const float* p_rel = (const float*)d_in[22];
    float* out = (float*)d_out;

    float* xw    = symaddr(g_xw);
    float* k_op  = symaddr(g_k_op);
    float* q_op  = symaddr(g_q_op);
    float* v_op  = symaddr(g_v_op);
    float* k_m   = symaddr(g_k_m);
    float* q_m   = symaddr(g_q_m);
    float* v_m   = symaddr(g_v_m);
    float* acc_op = symaddr(g_acc_op);
    float* acc_m  = symaddr(g_acc_m);
    int*   cur4  = (int*)symaddr(g_cur4);

    static bool attr_done = false;
    if (!attr_done) {
        cudaFuncSetAttribute(fused_kqv_scan,
                             cudaFuncAttributeMaxDynamicSharedMemorySize, DYN_BYTES);
        cudaFuncSetAttribute(gemm_final,
                             cudaFuncAttributeMaxDynamicSharedMemorySize, DYN_BYTES);
        attr_done = true;
    }

    cudaMemcpyAsync(xw, x_op, (size_t)NOP * DD * sizeof(float), cudaMemcpyDeviceToDevice);
    cudaMemsetAsync(cur4, 0, (size_t)4 * NOP * sizeof(int));

    // L1: temporal encoding + CSR degree count
    fused_temporal_count<<<TEMP_BLOCKS + 4 * CNT_BPT, 256>>>(
        delta_t, ei0, ei1, ei2, ei3, Wt, bt, ln_g, ln_b);

    // L2: 6 k/q/v GEMMs (double-buffered 3xTF32) + 4 CSR scans
    fused_kqv_scan<<<3 * TILES_ALL + 4, 256, DYN_BYTES>>>(
        xw, x_m, Wk, Wq, Wv, bk, bq, bv,
        k_op, q_op, v_op, k_m, q_m, v_m);

    // L3: relation transforms (tensor core) + CSR fill
    fused_rel_fill<<<REL_TC + 4 * CNT_BPT, 256>>>(a_rel, m_rel, ei0, ei1, ei2, ei3);

    // L4: both gathers
    fused_gather<<<GOP_BLOCKS + NMM, 256>>>(p_rel);

    // L5: both final GEMMs (double-buffered tensor core)
    gemm_final<<<TILES_ALL, 256, DYN_BYTES>>>(acc_op, acc_m, Wa, ba, xw, x_m, skip, out);
}

// round 17
// speedup vs baseline: 1.0812x; 1.0336x over previous
#include <cuda_runtime.h>
#include <cuda_fp16.h>
#include <math.h>
#include <stdint.h>

#define NOP 20000
#define NMM 500
#define DD  256
#define HH  8
#define DHD 32
#define TDE 16
#define EE  200000

#define TILES_OP 314   // 157 rowblocks x 2 colblocks
#define TILES_M  8     // 4 x 2
#define TILES_ALL (TILES_OP + TILES_M)

#define TEMP_BLOCKS 782            // ceil(EE/256), 256 edges per block
#define CNT_BPT 782                // count blocks per edge type: ceil(EE/256)
#define RELB_PER_H 313             // ceil(NOP/64) node-blocks per (type<3, head)
#define RELB_OP (RELB_PER_H * HH)  // 2504 per op-src type
#define RELB_M_PER_H 8             // ceil(NMM/64)
#define REL_TC (3 * RELB_OP + RELB_M_PER_H * HH)   // 7576
#define GOP_BLOCKS 2500            // NOP*32/256

#define SMP 20
#define PIECE (128 * SMP)          // 2560 u32 per matrix piece
#define BUFU32 (4 * PIECE)         // Ah|Al|Bh|Bl = 10240 u32 per buffer
#define DYN_BYTES (2 * BUFU32 * 4) // 81920 bytes

// ---------------- scratch ----------------
__device__ float g_xw[NOP * DD];
__device__ float g_k_op[NOP * DD];
__device__ float g_q_op[NOP * DD];
__device__ float g_v_op[NOP * DD];
__device__ float g_k_m[NMM * DD];
__device__ float g_q_m[NMM * DD];
__device__ float g_v_m[NMM * DD];
__device__ __half g_KTh[3][NOP * DD];   // fp16 transformed keys (op src types 0,1,2)
__device__ __half g_VTh[3][NOP * DD];
__device__ __half g_KTmh[NMM * DD];     // type 3 (machine src)
__device__ __half g_VTmh[NMM * DD];
__device__ float g_acc_op[NOP * DD];
__device__ float g_acc_m[NMM * DD];
__device__ int   g_off4[4][NOP + 1];
__device__ int   g_cur4[4][NOP];
__device__ int   g_esrc4[4][EE];

__device__ __forceinline__ float gelu_exact(float x) {
    return 0.5f * x * (1.0f + erff(x * 0.70710678118654752f));
}

__device__ __forceinline__ void red_add_v4(float* p, float a, float b, float c, float d) {
    asm volatile("red.global.add.v4.f32 [%0], {%1, %2, %3, %4};"
                 :: "l"(p), "f"(a), "f"(b), "f"(c), "f"(d) : "memory");
}

__device__ __forceinline__ uint32_t cvt_tf32(float x) {
    uint32_t r; asm("cvt.rna.tf32.f32 %0, %1;" : "=r"(r) : "f"(x)); return r;
}

__device__ __forceinline__ void mma_tf32(float* c, const uint32_t* a, const uint32_t* b) {
    asm volatile("mma.sync.aligned.m16n8k8.row.col.f32.tf32.tf32.f32 "
                 "{%0,%1,%2,%3}, {%4,%5,%6,%7}, {%8,%9}, {%0,%1,%2,%3};"
                 : "+f"(c[0]), "+f"(c[1]), "+f"(c[2]), "+f"(c[3])
                 : "r"(a[0]), "r"(a[1]), "r"(a[2]), "r"(a[3]),
                   "r"(b[0]), "r"(b[1]));
}

// ---------------- temporal encoding: 256 edges per block, 8 warps x 32 edges ----------------
__device__ void temporal_body(int blk,
                              const float* __restrict__ delta_t,
                              const int* __restrict__ ei_src,
                              const float* __restrict__ Wt,
                              const float* __restrict__ bt,
                              const float* __restrict__ ln_g,
                              const float* __restrict__ ln_b)
{
    __shared__ float Wts[TDE * DD];
    __shared__ float bts[DD], gs[DD], bs[DD];
    __shared__ float tr[8][DD];
    for (int idx = threadIdx.x; idx < DD * TDE; idx += blockDim.x) {
        int j = idx / TDE, i = idx % TDE;
        Wts[i * DD + j] = Wt[idx];
    }
    for (int idx = threadIdx.x; idx < DD; idx += blockDim.x) {
        bts[idx] = bt[idx]; gs[idx] = ln_g[idx]; bs[idx] = ln_b[idx];
    }
    __syncthreads();

    int warp = threadIdx.x >> 5;
    int lane = threadIdx.x & 31;

    float freqs[8];
    #pragma unroll
    for (int m = 0; m < 8; m++)
        freqs[m] = exp2f(-(float)m * (9.965784284662087f / 8.0f));  // 1000^{-m/8}

    #pragma unroll 1
    for (int t = 0; t < 32; t++) {
        int w = blk * 256 + warp * 32 + t;
        if (w >= EE) break;

        float dt = delta_t[w];
        int src = ei_src[w];

        float sn[8], cn[8];
        #pragma unroll
        for (int m = 0; m < 8; m++) sincosf(dt * freqs[m], &sn[m], &cn[m]);

        float pt[8];
        float lsum = 0.0f;
        #pragma unroll
        for (int jj = 0; jj < 8; jj++) {
            int j = lane + jj * 32;
            float s = bts[j];
            #pragma unroll
            for (int m = 0; m < 8; m++)
                s += sn[m] * Wts[(2 * m) * DD + j] + cn[m] * Wts[(2 * m + 1) * DD + j];
            pt[jj] = s;
            lsum += s;
        }
        #pragma unroll
        for (int o = 16; o; o >>= 1) lsum += __shfl_xor_sync(0xffffffffu, lsum, o);
        float mu = lsum * (1.0f / 256.0f);

        float lvar = 0.0f;
        #pragma unroll
        for (int jj = 0; jj < 8; jj++) { float d = pt[jj] - mu; lvar += d * d; }
        #pragma unroll
        for (int o = 16; o; o >>= 1) lvar += __shfl_xor_sync(0xffffffffu, lvar, o);
        float rstd = rsqrtf(lvar * (1.0f / 256.0f) + 1e-5f);

        #pragma unroll
        for (int jj = 0; jj < 8; jj++) {
            int j = lane + jj * 32;
            tr[warp][j] = (pt[jj] - mu) * rstd * gs[j] + bs[j];
        }
        __syncwarp();
        float4 y0 = *(const float4*)&tr[warp][lane * 8];
        float4 y1 = *(const float4*)&tr[warp][lane * 8 + 4];
        float* xp = &g_xw[(size_t)src * DD + lane * 8];
        red_add_v4(xp,     y0.x, y0.y, y0.z, y0.w);
        red_add_v4(xp + 4, y1.x, y1.y, y1.z, y1.w);
        __syncwarp();
    }
}

// ---------------- launch 1: temporal + CSR count ----------------
__global__ void __launch_bounds__(256) fused_temporal_count(
    const float* __restrict__ delta_t,
    const int* __restrict__ e0, const int* __restrict__ e1,
    const int* __restrict__ e2, const int* __restrict__ e3,
    const float* __restrict__ Wt, const float* __restrict__ bt,
    const float* __restrict__ ln_g, const float* __restrict__ ln_b)
{
    int b = blockIdx.x;
    if (b < TEMP_BLOCKS) {
        temporal_body(b, delta_t, e0, Wt, bt, ln_g, ln_b);
    } else {
        int cb = b - TEMP_BLOCKS;
        int ty = cb / CNT_BPT;
        int i = (cb % CNT_BPT) * 256 + threadIdx.x;
        if (i < EE) {
            const int* ei = (ty == 0) ? e0 : (ty == 1) ? e1 : (ty == 2) ? e2 : e3;
            atomicAdd(&g_cur4[ty][ei[EE + i]], 1);
        }
    }
}

// ---------------- tensor-core 3xTF32 GEMM tile: 128x128, K=256, double-buffered ----------------
__device__ __forceinline__ void split_store(uint32_t* H, uint32_t* L, int idx, float4 v) {
    uint32_t h0 = cvt_tf32(v.x), h1 = cvt_tf32(v.y), h2 = cvt_tf32(v.z), h3 = cvt_tf32(v.w);
    uint32_t l0 = cvt_tf32(v.x - __uint_as_float(h0));
    uint32_t l1 = cvt_tf32(v.y - __uint_as_float(h1));
    uint32_t l2 = cvt_tf32(v.z - __uint_as_float(h2));
    uint32_t l3 = cvt_tf32(v.w - __uint_as_float(h3));
    *(uint4*)&H[idx] = make_uint4(h0, h1, h2, h3);
    *(uint4*)&L[idx] = make_uint4(l0, l1, l2, l3);
}

template <bool FUSE>
__device__ __forceinline__ void gemm_tile_tc(
    uint32_t* smem,
    const float* __restrict__ A, const float* __restrict__ W,
    const float* __restrict__ bias, float* __restrict__ C, int N,
    const float* __restrict__ xsrc, float sa, int rowBase, int colBase)
{
    int tid = threadIdx.x;
    int lane = tid & 31;
    int wid = tid >> 5;
    int mwarp = wid >> 2;
    int nwarp = wid & 3;
    int grp  = lane >> 2;
    int tid4 = lane & 3;

    int row0 = tid >> 2, q0 = (tid & 3) * 4;
    int row1 = row0 + 64;
    int gr0 = rowBase + row0, gr1 = rowBase + row1;
    int gc0 = colBase + row0, gc1 = colBase + row1;

    float acc[4][4][4];
    #pragma unroll
    for (int i = 0; i < 4; i++)
        #pragma unroll
        for (int j = 0; j < 4; j++)
            #pragma unroll
            for (int r = 0; r < 4; r++) acc[i][j][r] = 0.0f;

    float4 av0, av1, bv0, bv1;
    auto ldg = [&](int kt) {
        av0 = make_float4(0.f, 0.f, 0.f, 0.f);
        av1 = make_float4(0.f, 0.f, 0.f, 0.f);
        if (gr0 < N) av0 = *(const float4*)(A + (size_t)gr0 * 256 + kt + q0);
        if (gr1 < N) av1 = *(const float4*)(A + (size_t)gr1 * 256 + kt + q0);
        if (FUSE) {
            av0.x = gelu_exact(av0.x); av0.y = gelu_exact(av0.y);
            av0.z = gelu_exact(av0.z); av0.w = gelu_exact(av0.w);
            av1.x = gelu_exact(av1.x); av1.y = gelu_exact(av1.y);
            av1.z = gelu_exact(av1.z); av1.w = gelu_exact(av1.w);
        }
        bv0 = *(const float4*)(W + (size_t)gc0 * 256 + kt + q0);
        bv1 = *(const float4*)(W + (size_t)gc1 * 256 + kt + q0);
    };
    auto sts = [&](int buf) {
        uint32_t* Ah = smem + buf * BUFU32;
        uint32_t* Al = Ah + PIECE;
        uint32_t* Bh = Ah + 2 * PIECE;
        uint32_t* Bl = Ah + 3 * PIECE;
        split_store(Ah, Al, row0 * SMP + q0, av0);
        split_store(Ah, Al, row1 * SMP + q0, av1);
        split_store(Bh, Bl, row0 * SMP + q0, bv0);
        split_store(Bh, Bl, row1 * SMP + q0, bv1);
    };

    ldg(0);
    sts(0);

    for (int it = 0; it < 16; it++) {
        __syncthreads();
        if (it < 15) ldg((it + 1) * 16);

        const uint32_t* Ah = smem + (it & 1) * BUFU32;
        const uint32_t* Al = Ah + PIECE;
        const uint32_t* Bh = Ah + 2 * PIECE;
        const uint32_t* Bl = Ah + 3 * PIECE;

        #pragma unroll
        for (int s = 0; s < 2; s++) {
            int kb = s * 8 + tid4;
            uint32_t ah[4][4], al[4][4];
            #pragma unroll
            for (int mt = 0; mt < 4; mt++) {
                int base = (mwarp * 64 + mt * 16 + grp) * SMP + kb;
                ah[mt][0] = Ah[base];            al[mt][0] = Al[base];
                ah[mt][1] = Ah[base + 8 * SMP];  al[mt][1] = Al[base + 8 * SMP];
                ah[mt][2] = Ah[base + 4];        al[mt][2] = Al[base + 4];
                ah[mt][3] = Ah[base + 8 * SMP + 4]; al[mt][3] = Al[base + 8 * SMP + 4];
            }
            uint32_t bh[4][2], bl[4][2];
            #pragma unroll
            for (int nt = 0; nt < 4; nt++) {
                int base = (nwarp * 32 + nt * 8 + grp) * SMP + kb;
                bh[nt][0] = Bh[base];     bl[nt][0] = Bl[base];
                bh[nt][1] = Bh[base + 4]; bl[nt][1] = Bl[base + 4];
            }
            #pragma unroll
            for (int mt = 0; mt < 4; mt++)
                #pragma unroll
                for (int nt = 0; nt < 4; nt++) {
                    mma_tf32(acc[mt][nt], ah[mt], bh[nt]);
                    mma_tf32(acc[mt][nt], ah[mt], bl[nt]);
                    mma_tf32(acc[mt][nt], al[mt], bh[nt]);
                }
        }
        if (it < 15) sts((it + 1) & 1);
    }

    #pragma unroll
    for (int mt = 0; mt < 4; mt++) {
        int r0g = rowBase + mwarp * 64 + mt * 16 + grp;
        int r1g = r0g + 8;
        #pragma unroll
        for (int nt = 0; nt < 4; nt++) {
            int c = colBase + nwarp * 32 + nt * 8 + tid4 * 2;
            float2 bi = *(const float2*)(bias + c);
            if (r0g < N) {
                float o0 = acc[mt][nt][0] + bi.x;
                float o1 = acc[mt][nt][1] + bi.y;
                if (FUSE) {
                    float2 xs = *(const float2*)(xsrc + (size_t)r0g * 256 + c);
                    o0 = sa * o0 + (1.0f - sa) * xs.x;
                    o1 = sa * o1 + (1.0f - sa) * xs.y;
                }
                *(float2*)(C + (size_t)r0g * 256 + c) = make_float2(o0, o1);
            }
            if (r1g < N) {
                float o2 = acc[mt][nt][2] + bi.x;
                float o3 = acc[mt][nt][3] + bi.y;
                if (FUSE) {
                    float2 xs = *(const float2*)(xsrc + (size_t)r1g * 256 + c);
                    o2 = sa * o2 + (1.0f - sa) * xs.x;
                    o3 = sa * o3 + (1.0f - sa) * xs.y;
                }
                *(float2*)(C + (size_t)r1g * 256 + c) = make_float2(o2, o3);
            }
        }
    }
}

// 256-thread exclusive scan of g_cur4[ty] -> g_off4[ty]; cur := offset
__device__ void csr_scan_body(int ty) {
    int Nd = (ty == 2) ? NMM : NOP;
    __shared__ int sp[256];
    int tid = threadIdx.x;
    int chunk = (Nd + 255) / 256;
    int beg = tid * chunk;
    int end = beg + chunk; if (end > Nd) end = Nd;
    int s = 0;
    for (int i = beg; i < end; i++) s += g_cur4[ty][i];
    sp[tid] = s;
    __syncthreads();
    #pragma unroll
    for (int o = 1; o < 256; o <<= 1) {
        int v = (tid >= o) ? sp[tid - o] : 0;
        __syncthreads();
        sp[tid] += v;
        __syncthreads();
    }
    int base = (tid == 0) ? 0 : sp[tid - 1];
    for (int i = beg; i < end; i++) {
        int d = g_cur4[ty][i];
        g_off4[ty][i] = base;
        g_cur4[ty][i] = base;
        base += d;
    }
    if (tid == 255) g_off4[ty][Nd] = sp[255];
}

// ---------------- launch 2: 6 k/q/v GEMMs + 4 CSR scans ----------------
__global__ void __launch_bounds__(256, 2) fused_kqv_scan(
    const float* __restrict__ Aop, const float* __restrict__ Am,
    const float* __restrict__ Wk, const float* __restrict__ Wq, const float* __restrict__ Wv,
    const float* __restrict__ bk, const float* __restrict__ bq, const float* __restrict__ bv,
    float* __restrict__ kop, float* __restrict__ qop, float* __restrict__ vop,
    float* __restrict__ km,  float* __restrict__ qm,  float* __restrict__ vm)
{
    extern __shared__ uint32_t dynsmem[];
    int b = blockIdx.x;
    if (b < 3 * TILES_ALL) {
        int z = b / TILES_ALL;
        int t = b % TILES_ALL;
        bool isM = t >= TILES_OP;
        int tt = isM ? t - TILES_OP : t;
        int rowBase = (tt >> 1) * 128;
        int colBase = (tt & 1) * 128;

        const float* A = isM ? Am : Aop;
        int N = isM ? NMM : NOP;
        const float* W = (z == 0 ? Wk : z == 1 ? Wq : Wv) + (isM ? DD * DD : 0);
        const float* bb = (z == 0 ? bk : z == 1 ? bq : bv) + (isM ? DD : 0);
        float* C = isM ? (z == 0 ? km : z == 1 ? qm : vm)
                       : (z == 0 ? kop : z == 1 ? qop : vop);
        gemm_tile_tc<false>(dynsmem, A, W, bb, C, N, nullptr, 0.0f, rowBase, colBase);
    } else {
        csr_scan_body(b - 3 * TILES_ALL);
    }
}

// ---------------- tensor-core rel transform -> fp16 output ----------------
__device__ void rel_body_tc(int e, int h, int xb,
                            const float* __restrict__ arel,
                            const float* __restrict__ mrel)
{
    int N = (e == 3) ? NMM : NOP;
    int nBase = xb * 64;
    if (nBase >= N) return;

    const float* ktab = (e == 3) ? g_k_m : g_k_op;
    const float* vtab = (e == 3) ? g_v_m : g_v_op;
    __half* KT = (e == 3) ? g_KTmh : g_KTh[e];
    __half* VT = (e == 3) ? g_VTmh : g_VTh[e];

    __shared__ uint32_t Ah[64 * 36], Al[64 * 36];
    __shared__ uint32_t Bah[32 * 36], Bal[32 * 36], Bmh[32 * 36], Bml[32 * 36];

    int tid = threadIdx.x, lane = tid & 31, wid = tid >> 5;
    int grp = lane >> 2, tid4 = lane & 3;
    int mt = wid & 3;
    int ntbase = (wid >> 2) * 2;

    for (int i = tid; i < 1024; i += 256) {
        int d = i >> 5, f = i & 31;
        float va = arel[((size_t)(e * HH + h)) * 1024 + i];
        float vm = mrel[((size_t)(e * HH + h)) * 1024 + i];
        uint32_t hh = cvt_tf32(va);
        Bah[f * 36 + d] = hh;
        Bal[f * 36 + d] = cvt_tf32(va - __uint_as_float(hh));
        hh = cvt_tf32(vm);
        Bmh[f * 36 + d] = hh;
        Bml[f * 36 + d] = cvt_tf32(vm - __uint_as_float(hh));
    }

    #pragma unroll
    for (int phase = 0; phase < 2; phase++) {
        const float* xt = phase ? vtab : ktab;
        __syncthreads();
        for (int q = tid; q < 512; q += 256) {
            int r = q >> 3, c4 = (q & 7) * 4;
            float4 v = make_float4(0.f, 0.f, 0.f, 0.f);
            if (nBase + r < N)
                v = *(const float4*)(xt + (size_t)(nBase + r) * 256 + h * 32 + c4);
            uint32_t h0 = cvt_tf32(v.x), h1 = cvt_tf32(v.y), h2 = cvt_tf32(v.z), h3 = cvt_tf32(v.w);
            int idx = r * 36 + c4;
            Ah[idx] = h0; Ah[idx + 1] = h1; Ah[idx + 2] = h2; Ah[idx + 3] = h3;
            Al[idx]     = cvt_tf32(v.x - __uint_as_float(h0));
            Al[idx + 1] = cvt_tf32(v.y - __uint_as_float(h1));
            Al[idx + 2] = cvt_tf32(v.z - __uint_as_float(h2));
            Al[idx + 3] = cvt_tf32(v.w - __uint_as_float(h3));
        }
        __syncthreads();

        const uint32_t* Bh = phase ? Bmh : Bah;
        const uint32_t* Bl = phase ? Bml : Bal;
        float acc[2][4];
        #pragma unroll
        for (int j = 0; j < 2; j++)
            #pragma unroll
            for (int r = 0; r < 4; r++) acc[j][r] = 0.0f;

        #pragma unroll
        for (int kc = 0; kc < 4; kc++) {
            int kb = kc * 8 + tid4;
            int ab = (mt * 16 + grp) * 36 + kb;
            uint32_t ah[4] = {Ah[ab], Ah[ab + 8 * 36], Ah[ab + 4], Ah[ab + 8 * 36 + 4]};
            uint32_t al[4] = {Al[ab], Al[ab + 8 * 36], Al[ab + 4], Al[ab + 8 * 36 + 4]};
            #pragma unroll
            for (int j = 0; j < 2; j++) {
                int bb = ((ntbase + j) * 8 + grp) * 36 + kb;
                uint32_t bh[2] = {Bh[bb], Bh[bb + 4]};
                uint32_t bl[2] = {Bl[bb], Bl[bb + 4]};
                mma_tf32(acc[j], ah, bh);
                mma_tf32(acc[j], ah, bl);
                mma_tf32(acc[j], al, bh);
            }
        }

        __half* OUT = phase ? VT : KT;
        int r0 = nBase + mt * 16 + grp;
        int r1 = r0 + 8;
        #pragma unroll
        for (int j = 0; j < 2; j++) {
            int c = (ntbase + j) * 8 + tid4 * 2;
            if (r0 < N)
                *(__half2*)(OUT + (size_t)r0 * 256 + h * 32 + c) =
                    __floats2half2_rn(acc[j][0], acc[j][1]);
            if (r1 < N)
                *(__half2*)(OUT + (size_t)r1 * 256 + h * 32 + c) =
                    __floats2half2_rn(acc[j][2], acc[j][3]);
        }
    }
}

// ---------------- launch 3: rel transforms (TC) + CSR fill ----------------
__global__ void __launch_bounds__(256) fused_rel_fill(
    const float* __restrict__ arel, const float* __restrict__ mrel,
    const int* __restrict__ e0, const int* __restrict__ e1,
    const int* __restrict__ e2, const int* __restrict__ e3)
{
    int b = blockIdx.x;
    if (b < 3 * RELB_OP) {
        int e = b / RELB_OP;
        int rem = b % RELB_OP;
        int h = rem / RELB_PER_H;
        int xb = rem % RELB_PER_H;
        rel_body_tc(e, h, xb, arel, mrel);
    } else if (b < REL_TC) {
        int b2 = b - 3 * RELB_OP;
        int h = b2 / RELB_M_PER_H;
        int xb = b2 % RELB_M_PER_H;
        rel_body_tc(3, h, xb, arel, mrel);
    } else {
        int cb = b - REL_TC;
        int ty = cb / CNT_BPT;
        int i = (cb % CNT_BPT) * 256 + threadIdx.x;
        if (i < EE) {
            const int* ei = (ty == 0) ? e0 : (ty == 1) ? e1 : (ty == 2) ? e2 : e3;
            int dst = ei[EE + i];
            int src = ei[i];
            int pos = atomicAdd(&g_cur4[ty][dst], 1);
            g_esrc4[ty][pos] = src;
        }
    }
}

// ---------------- fp16 gather helpers ----------------
// lane owns elements [lane*8, lane*8+8): one uint4 (8 halves) per table.
__device__ __forceinline__ void h8_to_f(const uint4& u, float* f) {
    const __half2* h = (const __half2*)&u;
    float2 a = __half22float2(h[0]);
    float2 b = __half22float2(h[1]);
    float2 c = __half22float2(h[2]);
    float2 d = __half22float2(h[3]);
    f[0] = a.x; f[1] = a.y; f[2] = b.x; f[3] = b.y;
    f[4] = c.x; f[5] = c.y; f[6] = d.x; f[7] = d.y;
}

// ---------------- gather bodies ----------------
__device__ void gather_op_body(int b, const float* __restrict__ prel)
{
    int w = b * 8 + (threadIdx.x >> 5);
    int lane = threadIdx.x & 31;
    if (w >= NOP) return;

    const float4* qp = (const float4*)(g_q_op + (size_t)w * 256);
    float4 q0 = qp[lane * 2], q1 = qp[lane * 2 + 1];
    float qv[8] = {q0.x, q0.y, q0.z, q0.w, q1.x, q1.y, q1.z, q1.w};
    int h = lane >> 2;

    float out[8] = {0.f, 0.f, 0.f, 0.f, 0.f, 0.f, 0.f, 0.f};

    #pragma unroll
    for (int pass = 0; pass < 3; pass++) {
        int e = (pass == 2) ? 3 : pass;
        const __half* KT = (pass == 2) ? g_KTmh : g_KTh[e];
        const __half* VT = (pass == 2) ? g_VTmh : g_VTh[e];
        float ps = prel[e * HH + h] * 0.17677669529663687f;   // 1/sqrt(32)

        int beg = g_off4[e][w], end = g_off4[e][w + 1];
        float num[8] = {0.f, 0.f, 0.f, 0.f, 0.f, 0.f, 0.f, 0.f};
        float den = 0.0f;
        #pragma unroll 2
        for (int j = beg; j < end; j++) {
            int src = g_esrc4[e][j];
            uint4 ku = ((const uint4*)(KT + (size_t)src * 256))[lane];
            uint4 vu = ((const uint4*)(VT + (size_t)src * 256))[lane];
            float kf[8], vf[8];
            h8_to_f(ku, kf);
            h8_to_f(vu, vf);
            float s = 0.0f;
            #pragma unroll
            for (int i = 0; i < 8; i++) s += qv[i] * kf[i];
            s += __shfl_xor_sync(0xffffffffu, s, 1);
            s += __shfl_xor_sync(0xffffffffu, s, 2);
            float ev = expf(s * ps);
            den += ev;
            #pragma unroll
            for (int i = 0; i < 8; i++) num[i] += ev * vf[i];
        }
        float inv = (den > 0.f) ? 1.0f / den : 0.0f;
        #pragma unroll
        for (int i = 0; i < 8; i++) out[i] += num[i] * inv;
    }

    float* ap = g_acc_op + (size_t)w * 256 + lane * 8;
    *(float4*)(ap)     = make_float4(out[0], out[1], out[2], out[3]);
    *(float4*)(ap + 4) = make_float4(out[4], out[5], out[6], out[7]);
}

__device__ void gather_m_body(int n, const float* __restrict__ prel)
{
    __shared__ float snum[8][256];
    __shared__ float sden[8][8];
    int warp = threadIdx.x >> 5, lane = threadIdx.x & 31;
    int h = lane >> 2;
    int beg = g_off4[2][n], end = g_off4[2][n + 1];

    const float4* qp = (const float4*)(g_q_m + (size_t)n * 256);
    float4 q0 = qp[lane * 2], q1 = qp[lane * 2 + 1];
    float qv[8] = {q0.x, q0.y, q0.z, q0.w, q1.x, q1.y, q1.z, q1.w};
    float ps = prel[2 * HH + h] * 0.17677669529663687f;

    float num[8] = {0.f, 0.f, 0.f, 0.f, 0.f, 0.f, 0.f, 0.f};
    float den = 0.0f;

    for (int j = beg + warp; j < end; j += 8) {
        int src = g_esrc4[2][j];
        uint4 ku = ((const uint4*)(g_KTh[2] + (size_t)src * 256))[lane];
        uint4 vu = ((const uint4*)(g_VTh[2] + (size_t)src * 256))[lane];
        float kf[8], vf[8];
        h8_to_f(ku, kf);
        h8_to_f(vu, vf);
        float s = 0.0f;
        #pragma unroll
        for (int i = 0; i < 8; i++) s += qv[i] * kf[i];
        s += __shfl_xor_sync(0xffffffffu, s, 1);
        s += __shfl_xor_sync(0xffffffffu, s, 2);
        float ev = expf(s * ps);
        den += ev;
        #pragma unroll
        for (int i = 0; i < 8; i++) num[i] += ev * vf[i];
    }
    #pragma unroll
    for (int i = 0; i < 8; i += 4)
        *(float4*)&snum[warp][lane * 8 + i] = make_float4(num[i], num[i+1], num[i+2], num[i+3]);
    if ((lane & 3) == 0) sden[warp][h] = den;
    __syncthreads();

    {
        int c = threadIdx.x;
        float tot = 0.0f;
        #pragma unroll
        for (int ww = 0; ww < 8; ww++) tot += snum[ww][c];
        int hh = c >> 5;
        float d = 0.0f;
        #pragma unroll
        for (int ww = 0; ww < 8; ww++) d += sden[ww][hh];
        g_acc_m[(size_t)n * 256 + c] = (d > 0.f) ? tot / d : 0.0f;
    }
}

// ---------------- launch 4: both gathers ----------------
__global__ void __launch_bounds__(256) fused_gather(const float* __restrict__ prel)
{
    int b = blockIdx.x;
    if (b < GOP_BLOCKS) gather_op_body(b, prel);
    else                gather_m_body(b - GOP_BLOCKS, prel);
}

// ---------------- launch 5: both final FUSE GEMMs ----------------
__global__ void __launch_bounds__(256, 2) gemm_final(
    const float* __restrict__ accop, const float* __restrict__ accm,
    const float* __restrict__ Wa, const float* __restrict__ ba,
    const float* __restrict__ xop, const float* __restrict__ xm,
    const float* __restrict__ skipv, float* __restrict__ out)
{
    extern __shared__ uint32_t dynsmem[];
    int t = blockIdx.x;
    bool isM = t >= TILES_OP;
    int tt = isM ? t - TILES_OP : t;
    int rowBase = (tt >> 1) * 128;
    int colBase = (tt & 1) * 128;

    const float* A = isM ? accm : accop;
    int N = isM ? NMM : NOP;
    const float* W = Wa + (isM ? DD * DD : 0);
    const float* b = ba + (isM ? DD : 0);
    const float* xs = isM ? xm : xop;
    float* C = out + (isM ? (size_t)NOP * DD : 0);
    float sa = 1.0f / (1.0f + expf(-skipv[isM ? 1 : 0]));

    gemm_tile_tc<true>(dynsmem, A, W, b, C, N, xs, sa, rowBase, colBase);
}

// ---------------- host side ----------------
static float* symaddr(const void* sym) {
    void* p = nullptr;
    cudaGetSymbolAddress(&p, sym);
    return (float*)p;
}

extern "C" void kernel_launch(void* const* d_in, const int* in_sizes, int n_in,
                              void* d_out, int out_size)
{
    const float* x_op    = (const float*)d_in[0];
    const float* x_m     = (const float*)d_in[1];
    const float* delta_t = (const float*)d_in[2];
    const int*   ei0 = (const int*)d_in[3];
    const int*   ei1 = (const int*)d_in[4];
    const int*   ei2 = (const int*)d_in[5];
    const int*   ei3 = (const int*)d_in[6];
    const float* Wt   = (const float*)d_in[7];
    const float* bt   = (const float*)d_in[8];
    const float* ln_g = (const float*)d_in[9];
    const float* ln_b = (const float*)d_in[10];
    const float* Wk   = (const float*)d_in[11];
    const float* bk   = (const float*)d_in[12];
    const float* Wq   = (const float*)d_in[13];
    const float* bq   = (const float*)d_in[14];
    const float* Wv   = (const float*)d_in[15];
    const float* bv   = (const float*)d_in[16];
    const float* Wa   = (const float*)d_in[17];
    const float* ba   = (const float*)d_in[18];
    const float* skip = (const float*)d_in[19];
    const float* a_rel = (const float*)d_in[20];
    const float* m_rel = (const float*)d_in[21];
    const float* p_rel = (const float*)d_in[22];
    float* out = (float*)d_out;

    float* xw    = symaddr(g_xw);
    float* k_op  = symaddr(g_k_op);
    float* q_op  = symaddr(g_q_op);
    float* v_op  = symaddr(g_v_op);
    float* k_m   = symaddr(g_k_m);
    float* q_m   = symaddr(g_q_m);
    float* v_m   = symaddr(g_v_m);
    float* acc_op = symaddr(g_acc_op);
    float* acc_m  = symaddr(g_acc_m);
    int*   cur4  = (int*)symaddr(g_cur4);

    static bool attr_done = false;
    if (!attr_done) {
        cudaFuncSetAttribute(fused_kqv_scan,
                             cudaFuncAttributeMaxDynamicSharedMemorySize, DYN_BYTES);
        cudaFuncSetAttribute(gemm_final,
                             cudaFuncAttributeMaxDynamicSharedMemorySize, DYN_BYTES);
        attr_done = true;
    }

    cudaMemcpyAsync(xw, x_op, (size_t)NOP * DD * sizeof(float), cudaMemcpyDeviceToDevice);
    cudaMemsetAsync(cur4, 0, (size_t)4 * NOP * sizeof(int));

    // L1: temporal encoding + CSR degree count
    fused_temporal_count<<<TEMP_BLOCKS + 4 * CNT_BPT, 256>>>(
        delta_t, ei0, ei1, ei2, ei3, Wt, bt, ln_g, ln_b);

    // L2: 6 k/q/v GEMMs (double-buffered 3xTF32) + 4 CSR scans
    fused_kqv_scan<<<3 * TILES_ALL + 4, 256, DYN_BYTES>>>(
        xw, x_m, Wk, Wq, Wv, bk, bq, bv,
        k_op, q_op, v_op, k_m, q_m, v_m);

    // L3: relation transforms (tensor core, fp16 out) + CSR fill
    fused_rel_fill<<<REL_TC + 4 * CNT_BPT, 256>>>(a_rel, m_rel, ei0, ei1, ei2, ei3);

    // L4: both gathers (fp16 K̃/Ṽ)
    fused_gather<<<GOP_BLOCKS + NMM, 256>>>(p_rel);

    // L5: both final GEMMs (double-buffered tensor core)
    gemm_final<<<TILES_ALL, 256, DYN_BYTES>>>(acc_op, acc_m, Wa, ba, xw, x_m, skip, out);
}